// round 7
// baseline (speedup 1.0000x reference)
#include <cuda_runtime.h>
#include <cuda_fp16.h>
#include <cstdint>

// Problem constants (fixed: B=8, T=2048, D=2048)
#define B_SZ 8
#define T_SZ 2048
#define D_SZ 2048
#define M_SZ (B_SZ * T_SZ)        // 16384
#define CH_SZ (B_SZ * D_SZ)       // 16384 channels
#define SEG_LEN 256
#define N_SEG (T_SZ / SEG_LEN)    // 8

// ---------------- device scratch (static: no runtime allocation) ------------
__device__ __half g_xh[(size_t)M_SZ * D_SZ];     // fp16(x)
__device__ __half g_wh[(size_t)3 * D_SZ * D_SZ]; // fp16(W) for Wk,Wv,Wr
__device__ float g_k[(size_t)M_SZ * D_SZ];
__device__ float g_v[(size_t)M_SZ * D_SZ];
__device__ float g_r[(size_t)M_SZ * D_SZ];
__device__ float g_cn[(size_t)N_SEG * CH_SZ];
__device__ float g_cd[(size_t)N_SEG * CH_SZ];

// ---------------- helpers -----------------------------------------------------
__device__ __forceinline__ uint32_t smem_u32(const void* p) {
    uint32_t a;
    asm("{ .reg .u64 t; cvta.to.shared.u64 t, %1; cvt.u32.u64 %0, t; }" : "=r"(a) : "l"(p));
    return a;
}
__device__ __forceinline__ void cp16(uint32_t dst, const void* src) {
    asm volatile("cp.async.cg.shared.global [%0], [%1], 16;" :: "r"(dst), "l"(src));
}
// zfill variant: src_sz = 0 -> write 16 zero bytes
__device__ __forceinline__ void cp16z(uint32_t dst, const void* src, uint32_t src_sz) {
    asm volatile("cp.async.cg.shared.global [%0], [%1], 16, %2;"
                 :: "r"(dst), "l"(src), "r"(src_sz));
}
#define SWZ128(o) ((o) ^ (((o) >> 3) & 0x70))

__device__ __forceinline__ void ldsm_x4(uint32_t* r, uint32_t addr) {
    asm volatile("ldmatrix.sync.aligned.m8n8.x4.shared.b16 {%0,%1,%2,%3}, [%4];"
                 : "=r"(r[0]), "=r"(r[1]), "=r"(r[2]), "=r"(r[3]) : "r"(addr));
}
__device__ __forceinline__ void mma16816(float* c, const uint32_t* a, const uint32_t* b) {
    asm volatile(
        "mma.sync.aligned.m16n8k16.row.col.f32.f16.f16.f32 "
        "{%0,%1,%2,%3}, {%4,%5,%6,%7}, {%8,%9}, {%0,%1,%2,%3};"
        : "+f"(c[0]), "+f"(c[1]), "+f"(c[2]), "+f"(c[3])
        : "r"(a[0]), "r"(a[1]), "r"(a[2]), "r"(a[3]), "r"(b[0]), "r"(b[1]));
}

// ---------------- conversion: fp32 -> fp16 -------------------------------------
__global__ void convert_x_kernel(const float* __restrict__ x) {
    size_t i4 = (size_t)blockIdx.x * blockDim.x + threadIdx.x;
    if (i4 >= (size_t)M_SZ * D_SZ / 4) return;
    size_t i = i4 * 4;
    float4 v = *(const float4*)(x + i);
    __half2* hp = (__half2*)(g_xh + i);
    hp[0] = __halves2half2(__float2half_rn(v.x), __float2half_rn(v.y));
    hp[1] = __halves2half2(__float2half_rn(v.z), __float2half_rn(v.w));
}

__global__ void convert_w_kernel(const float* __restrict__ Wk,
                                 const float* __restrict__ Wv,
                                 const float* __restrict__ Wr) {
    const int z = blockIdx.y;
    const float* W = (z == 0) ? Wk : (z == 1) ? Wv : Wr;
    size_t i4 = (size_t)blockIdx.x * blockDim.x + threadIdx.x;
    if (i4 >= (size_t)D_SZ * D_SZ / 4) return;
    size_t i = i4 * 4;
    float4 v = *(const float4*)(W + i);
    __half2* op = (__half2*)(g_wh + (size_t)z * D_SZ * D_SZ + i);
    op[0] = __halves2half2(__float2half_rn(v.x), __float2half_rn(v.y));
    op[1] = __halves2half2(__float2half_rn(v.z), __float2half_rn(v.w));
}

// ---------------- HMMA GEMM: C[m,n] = sum_k A[m,k]*W[n,k] ---------------------
// Single fp16 MMA pass. Time shift read-side (zfill at t==0).
// Tile 128x128, BK=64, 3-stage cp.async, 2 CTA/SM, ONE sync per chunk:
// at top of chunk c, stage (c-1)%3 is free -> issue load of chunk c+2 there.
#define BM 128
#define BN 128
#define BK 64
#define N_CHUNK (D_SZ / BK)        // 32
#define TILE_B 16384               // 128 rows x 128B
#define STAGE_BYTES (2 * TILE_B)   // A, B
#define N_STAGE 3
#define GEMM_SMEM (N_STAGE * STAGE_BYTES)   // 96 KB

__global__ __launch_bounds__(256, 2)
void gemm_hmma_kernel() {
    extern __shared__ char smem[];
    const uint32_t sbase = smem_u32(smem);
    const int tid = threadIdx.x;
    const int wid = tid >> 5;
    const int lane = tid & 31;
    const int wm = wid & 1;          // 2 warps over M
    const int wn = wid >> 1;         // 4 warps over N

    const int z = blockIdx.z;
    const int m0 = blockIdx.y * BM;
    const int n0 = blockIdx.x * BN;
    const bool shift = (z < 2);

    const __half* B_h = g_wh + (size_t)z * D_SZ * D_SZ;
    float* C = (z == 0) ? g_k : (z == 1) ? g_v : g_r;

    float acc[4][4][4];
#pragma unroll
    for (int i = 0; i < 4; i++)
#pragma unroll
        for (int j = 0; j < 4; j++)
#pragma unroll
            for (int q = 0; q < 4; q++) acc[i][j][q] = 0.f;

    // stage loader: K-chunk c into stage s
    auto load_stage = [&](int c, int s) {
        const int kt = c * BK;
        const uint32_t st = sbase + s * STAGE_BYTES;
#pragma unroll
        for (int it = 0; it < 4; it++) {
            const int i = tid + it * 256;
            const int row = i >> 3, seg = i & 7;
            const uint32_t sw = SWZ128((uint32_t)(row * 128 + seg * 16));
            // A (time shift handled here; zero row at t==0)
            const int rm = m0 + row;
            uint32_t sz = 16;
            int srow = rm;
            if (shift) {
                if ((rm & (T_SZ - 1)) == 0) sz = 0;
                else srow = rm - 1;
            }
            cp16z(st + sw, g_xh + (size_t)srow * D_SZ + kt + seg * 8, sz);
            // B
            cp16(st + TILE_B + sw, B_h + (size_t)(n0 + row) * D_SZ + kt + seg * 8);
        }
        asm volatile("cp.async.commit_group;" ::: "memory");
    };

    load_stage(0, 0);
    load_stage(1, 1);
    load_stage(2, 2);

    const int a_row = lane & 15;
    const int a_half = lane >> 4;
    const int b_nr = (lane & 7) + ((lane >> 4) << 3);
    const int b_half = (lane >> 3) & 1;

    int s = 0;       // stage of current chunk
    int fs = 2;      // (c-1)%3 tracker: stage freed at top of chunk c (valid for c>=1)
    for (int c = 0; c < N_CHUNK; c++) {
        // group c must be done. Issued so far: 0..min(c+1, N-1).
        if (c == 0)                 asm volatile("cp.async.wait_group 2;" ::: "memory");
        else if (c == N_CHUNK - 1)  asm volatile("cp.async.wait_group 0;" ::: "memory");
        else                        asm volatile("cp.async.wait_group 1;" ::: "memory");
        __syncthreads();   // all warps done with chunk c-1 -> stage fs free

        if (c >= 1 && c + 2 < N_CHUNK) load_stage(c + 2, fs);

        const uint32_t sA = sbase + s * STAGE_BYTES;
        const uint32_t sB = sA + TILE_B;

#pragma unroll
        for (int ks = 0; ks < 4; ks++) {
            uint32_t aa[4][4], bb[2][4];
#pragma unroll
            for (int mi = 0; mi < 4; mi++) {
                const uint32_t off = SWZ128(
                    (uint32_t)((wm * 64 + mi * 16 + a_row) * 128 + ks * 32 + a_half * 16));
                ldsm_x4(aa[mi], sA + off);
            }
#pragma unroll
            for (int j = 0; j < 2; j++) {
                const uint32_t off = SWZ128(
                    (uint32_t)((wn * 32 + j * 16 + b_nr) * 128 + ks * 32 + b_half * 16));
                ldsm_x4(bb[j], sB + off);
            }
#pragma unroll
            for (int mi = 0; mi < 4; mi++)
#pragma unroll
                for (int ni = 0; ni < 4; ni++)
                    mma16816(acc[mi][ni], aa[mi], &bb[ni >> 1][(ni & 1) * 2]);
        }
        fs = s;
        s = (s == N_STAGE - 1) ? 0 : s + 1;
    }

    // epilogue
#pragma unroll
    for (int mi = 0; mi < 4; mi++) {
        const int gm = m0 + wm * 64 + mi * 16 + (lane >> 2);
#pragma unroll
        for (int ni = 0; ni < 4; ni++) {
            const int gn = n0 + wn * 32 + ni * 8 + (lane & 3) * 2;
            float* p0 = C + (size_t)gm * D_SZ + gn;
            float* p1 = p0 + 8 * D_SZ;
            *(float2*)p0 = make_float2(acc[mi][ni][0], acc[mi][ni][1]);
            *(float2*)p1 = make_float2(acc[mi][ni][2], acc[mi][ni][3]);
        }
    }
}

// ---------------- split WKV scan (4 channels/thread, float4) -------------------
__device__ __forceinline__ float4 exp4(float4 a) {
    return make_float4(expf(a.x), expf(a.y), expf(a.z), expf(a.w));
}

__global__ void wkv_p1_kernel(const float* __restrict__ time_decay) {
    const int gid = blockIdx.x * blockDim.x + threadIdx.x;   // < N_SEG*CH/4
    const int c4 = gid & (CH_SZ / 4 - 1);
    const int seg = gid >> 12;          // CH/4 = 4096
    const int c = c4 * 4;
    const int d = c & (D_SZ - 1);
    const int b = c >> 11;

    const float4 tdv = *(const float4*)(time_decay + d);
    const float4 w4 = make_float4(expf(-expf(tdv.x)), expf(-expf(tdv.y)),
                                  expf(-expf(tdv.z)), expf(-expf(tdv.w)));

    const size_t base = (size_t)b * T_SZ * D_SZ + (size_t)seg * SEG_LEN * D_SZ + d;
    const float* kp = g_k + base;
    const float* vp = g_v + base;

    float4 num = make_float4(0.f, 0.f, 0.f, 0.f);
    float4 den = make_float4(0.f, 0.f, 0.f, 0.f);

    for (int t = 0; t < SEG_LEN; t += 4) {
        float4 kk[4], vv[4];
#pragma unroll
        for (int i = 0; i < 4; i++) {
            const size_t o = (size_t)(t + i) * D_SZ;
            kk[i] = *(const float4*)(kp + o);
            vv[i] = *(const float4*)(vp + o);
        }
#pragma unroll
        for (int i = 0; i < 4; i++) {
            const float4 ek = exp4(kk[i]);
            num.x = fmaf(w4.x, num.x, ek.x * vv[i].x);
            num.y = fmaf(w4.y, num.y, ek.y * vv[i].y);
            num.z = fmaf(w4.z, num.z, ek.z * vv[i].z);
            num.w = fmaf(w4.w, num.w, ek.w * vv[i].w);
            den.x = fmaf(w4.x, den.x, ek.x);
            den.y = fmaf(w4.y, den.y, ek.y);
            den.z = fmaf(w4.z, den.z, ek.z);
            den.w = fmaf(w4.w, den.w, ek.w);
        }
    }
    *(float4*)(g_cn + (size_t)seg * CH_SZ + c) = num;
    *(float4*)(g_cd + (size_t)seg * CH_SZ + c) = den;
}

__global__ void wkv_p2_kernel(const float* __restrict__ time_decay,
                              const float* __restrict__ x,
                              float* __restrict__ out) {
    const int gid = blockIdx.x * blockDim.x + threadIdx.x;
    const int c4 = gid & (CH_SZ / 4 - 1);
    const int seg = gid >> 12;
    const int c = c4 * 4;
    const int d = c & (D_SZ - 1);
    const int b = c >> 11;

    const float4 tdv = *(const float4*)(time_decay + d);
    const float4 e4 = make_float4(expf(tdv.x), expf(tdv.y), expf(tdv.z), expf(tdv.w));
    const float4 w4 = make_float4(expf(-e4.x), expf(-e4.y), expf(-e4.z), expf(-e4.w));
    const float4 wl = make_float4(expf(-(float)SEG_LEN * e4.x), expf(-(float)SEG_LEN * e4.y),
                                  expf(-(float)SEG_LEN * e4.z), expf(-(float)SEG_LEN * e4.w));

    float4 num = make_float4(0.f, 0.f, 0.f, 0.f);
    float4 den = make_float4(0.f, 0.f, 0.f, 0.f);
    for (int i = 0; i < seg; i++) {
        const float4 cn = *(const float4*)(g_cn + (size_t)i * CH_SZ + c);
        const float4 cd = *(const float4*)(g_cd + (size_t)i * CH_SZ + c);
        num.x = fmaf(wl.x, num.x, cn.x);
        num.y = fmaf(wl.y, num.y, cn.y);
        num.z = fmaf(wl.z, num.z, cn.z);
        num.w = fmaf(wl.w, num.w, cn.w);
        den.x = fmaf(wl.x, den.x, cd.x);
        den.y = fmaf(wl.y, den.y, cd.y);
        den.z = fmaf(wl.z, den.z, cd.z);
        den.w = fmaf(wl.w, den.w, cd.w);
    }

    const size_t base = (size_t)b * T_SZ * D_SZ + (size_t)seg * SEG_LEN * D_SZ + d;
    const float* kp = g_k + base;
    const float* vp = g_v + base;
    const float* rp = g_r + base;
    float* op = out + base;

    for (int t = 0; t < SEG_LEN; t += 4) {
        float4 kk[4], vv[4], rr[4];
#pragma unroll
        for (int i = 0; i < 4; i++) {
            const size_t o = (size_t)(t + i) * D_SZ;
            kk[i] = *(const float4*)(kp + o);
            vv[i] = *(const float4*)(vp + o);
            rr[i] = *(const float4*)(rp + o);
        }
#pragma unroll
        for (int i = 0; i < 4; i++) {
            const float4 ek = exp4(kk[i]);
            num.x = fmaf(w4.x, num.x, ek.x * vv[i].x);
            num.y = fmaf(w4.y, num.y, ek.y * vv[i].y);
            num.z = fmaf(w4.z, num.z, ek.z * vv[i].z);
            num.w = fmaf(w4.w, num.w, ek.w * vv[i].w);
            den.x = fmaf(w4.x, den.x, ek.x);
            den.y = fmaf(w4.y, den.y, ek.y);
            den.z = fmaf(w4.z, den.z, ek.z);
            den.w = fmaf(w4.w, den.w, ek.w);
            float4 o4;
            o4.x = rr[i].x * num.x / (den.x + 1e-8f);
            o4.y = rr[i].y * num.y / (den.y + 1e-8f);
            o4.z = rr[i].z * num.z / (den.z + 1e-8f);
            o4.w = rr[i].w * num.w / (den.w + 1e-8f);
            *(float4*)(op + (size_t)(t + i) * D_SZ) = o4;
        }
    }

    if (seg == 0) {
        float* out2 = out + (size_t)B_SZ * T_SZ * D_SZ;
        *(float4*)(out2 + c) =
            *(const float4*)(x + (size_t)b * T_SZ * D_SZ + (size_t)(T_SZ - 2) * D_SZ + d);
    }
}

// ---------------- launch --------------------------------------------------------
extern "C" void kernel_launch(void* const* d_in, const int* in_sizes, int n_in,
                              void* d_out, int out_size)
{
    const float* x  = (const float*)d_in[0];
    const float* Wk = (const float*)d_in[1];
    const float* Wv = (const float*)d_in[2];
    const float* Wr = (const float*)d_in[3];
    const float* td = (const float*)d_in[4];
    float* out = (float*)d_out;

    cudaFuncSetAttribute(gemm_hmma_kernel,
                         cudaFuncAttributeMaxDynamicSharedMemorySize, GEMM_SMEM);

    convert_x_kernel<<<(M_SZ * (size_t)D_SZ / 4 + 255) / 256, 256>>>(x);
    {
        dim3 g((D_SZ * (size_t)D_SZ / 4 + 255) / 256, 3);
        convert_w_kernel<<<g, 256>>>(Wk, Wv, Wr);
    }

    dim3 gg(D_SZ / BN, M_SZ / BM, 3);   // (16, 128, 3)
    gemm_hmma_kernel<<<gg, 256, GEMM_SMEM>>>();

    const int total4 = N_SEG * CH_SZ / 4;    // 32768 threads
    wkv_p1_kernel<<<total4 / 256, 256>>>(td);
    wkv_p2_kernel<<<total4 / 256, 256>>>(td, x, out);
}

// round 8
// speedup vs baseline: 1.0905x; 1.0905x over previous
#include <cuda_runtime.h>
#include <cuda_fp16.h>
#include <cstdint>

// Problem constants (fixed: B=8, T=2048, D=2048)
#define B_SZ 8
#define T_SZ 2048
#define D_SZ 2048
#define M_SZ (B_SZ * T_SZ)        // 16384
#define CH_SZ (B_SZ * D_SZ)       // 16384 channels
#define SEG_LEN 256
#define N_SEG (T_SZ / SEG_LEN)    // 8

// ---------------- device scratch (static: no runtime allocation) ------------
__device__ __half g_xh[(size_t)M_SZ * D_SZ];     // fp16(x)
__device__ __half g_wh[(size_t)3 * D_SZ * D_SZ]; // fp16(W) for Wk,Wv,Wr
__device__ float g_k[(size_t)M_SZ * D_SZ];
__device__ float g_v[(size_t)M_SZ * D_SZ];
__device__ float g_r[(size_t)M_SZ * D_SZ];
__device__ float g_cn[(size_t)N_SEG * CH_SZ];
__device__ float g_cd[(size_t)N_SEG * CH_SZ];

// ---------------- helpers -----------------------------------------------------
__device__ __forceinline__ uint32_t smem_u32(const void* p) {
    uint32_t a;
    asm("{ .reg .u64 t; cvta.to.shared.u64 t, %1; cvt.u32.u64 %0, t; }" : "=r"(a) : "l"(p));
    return a;
}
__device__ __forceinline__ void cp16(uint32_t dst, const void* src) {
    asm volatile("cp.async.cg.shared.global [%0], [%1], 16;" :: "r"(dst), "l"(src));
}
// zfill variant: src_sz = 0 -> write 16 zero bytes
__device__ __forceinline__ void cp16z(uint32_t dst, const void* src, uint32_t src_sz) {
    asm volatile("cp.async.cg.shared.global [%0], [%1], 16, %2;"
                 :: "r"(dst), "l"(src), "r"(src_sz));
}
#define SWZ128(o) ((o) ^ (((o) >> 3) & 0x70))

__device__ __forceinline__ void ldsm_x4(uint32_t* r, uint32_t addr) {
    asm volatile("ldmatrix.sync.aligned.m8n8.x4.shared.b16 {%0,%1,%2,%3}, [%4];"
                 : "=r"(r[0]), "=r"(r[1]), "=r"(r[2]), "=r"(r[3]) : "r"(addr));
}
__device__ __forceinline__ void mma16816(float* c, const uint32_t* a, const uint32_t* b) {
    asm volatile(
        "mma.sync.aligned.m16n8k16.row.col.f32.f16.f16.f32 "
        "{%0,%1,%2,%3}, {%4,%5,%6,%7}, {%8,%9}, {%0,%1,%2,%3};"
        : "+f"(c[0]), "+f"(c[1]), "+f"(c[2]), "+f"(c[3])
        : "r"(a[0]), "r"(a[1]), "r"(a[2]), "r"(a[3]), "r"(b[0]), "r"(b[1]));
}

// ---------------- conversion: fp32 -> fp16 -------------------------------------
__global__ void convert_x_kernel(const float* __restrict__ x) {
    size_t i4 = (size_t)blockIdx.x * blockDim.x + threadIdx.x;
    if (i4 >= (size_t)M_SZ * D_SZ / 4) return;
    size_t i = i4 * 4;
    float4 v = *(const float4*)(x + i);
    __half2* hp = (__half2*)(g_xh + i);
    hp[0] = __halves2half2(__float2half_rn(v.x), __float2half_rn(v.y));
    hp[1] = __halves2half2(__float2half_rn(v.z), __float2half_rn(v.w));
}

__global__ void convert_w_kernel(const float* __restrict__ Wk,
                                 const float* __restrict__ Wv,
                                 const float* __restrict__ Wr) {
    const int z = blockIdx.y;
    const float* W = (z == 0) ? Wk : (z == 1) ? Wv : Wr;
    size_t i4 = (size_t)blockIdx.x * blockDim.x + threadIdx.x;
    if (i4 >= (size_t)D_SZ * D_SZ / 4) return;
    size_t i = i4 * 4;
    float4 v = *(const float4*)(W + i);
    __half2* op = (__half2*)(g_wh + (size_t)z * D_SZ * D_SZ + i);
    op[0] = __halves2half2(__float2half_rn(v.x), __float2half_rn(v.y));
    op[1] = __halves2half2(__float2half_rn(v.z), __float2half_rn(v.w));
}

// ---------------- HMMA GEMM: C[m,n] = sum_k A[m,k]*W[n,k] ---------------------
// Single fp16 MMA pass. Time shift read-side (zfill at t==0).
// Tile 128x128, BK=64, 3-stage cp.async, 2 CTA/SM, ONE sync per chunk:
// at top of chunk c, stage (c-1)%3 is free -> issue load of chunk c+2 there.
#define BM 128
#define BN 128
#define BK 64
#define N_CHUNK (D_SZ / BK)        // 32
#define TILE_B 16384               // 128 rows x 128B
#define STAGE_BYTES (2 * TILE_B)   // A, B
#define N_STAGE 3
#define GEMM_SMEM (N_STAGE * STAGE_BYTES)   // 96 KB

__global__ __launch_bounds__(256, 2)
void gemm_hmma_kernel() {
    extern __shared__ char smem[];
    const uint32_t sbase = smem_u32(smem);
    const int tid = threadIdx.x;
    const int wid = tid >> 5;
    const int lane = tid & 31;
    const int wm = wid & 1;          // 2 warps over M
    const int wn = wid >> 1;         // 4 warps over N

    const int z = blockIdx.z;
    const int m0 = blockIdx.y * BM;
    const int n0 = blockIdx.x * BN;
    const bool shift = (z < 2);

    const __half* B_h = g_wh + (size_t)z * D_SZ * D_SZ;
    float* C = (z == 0) ? g_k : (z == 1) ? g_v : g_r;

    float acc[4][4][4];
#pragma unroll
    for (int i = 0; i < 4; i++)
#pragma unroll
        for (int j = 0; j < 4; j++)
#pragma unroll
            for (int q = 0; q < 4; q++) acc[i][j][q] = 0.f;

    // stage loader: K-chunk c into stage s
    auto load_stage = [&](int c, int s) {
        const int kt = c * BK;
        const uint32_t st = sbase + s * STAGE_BYTES;
#pragma unroll
        for (int it = 0; it < 4; it++) {
            const int i = tid + it * 256;
            const int row = i >> 3, seg = i & 7;
            const uint32_t sw = SWZ128((uint32_t)(row * 128 + seg * 16));
            // A (time shift handled here; zero row at t==0)
            const int rm = m0 + row;
            uint32_t sz = 16;
            int srow = rm;
            if (shift) {
                if ((rm & (T_SZ - 1)) == 0) sz = 0;
                else srow = rm - 1;
            }
            cp16z(st + sw, g_xh + (size_t)srow * D_SZ + kt + seg * 8, sz);
            // B
            cp16(st + TILE_B + sw, B_h + (size_t)(n0 + row) * D_SZ + kt + seg * 8);
        }
        asm volatile("cp.async.commit_group;" ::: "memory");
    };

    load_stage(0, 0);
    load_stage(1, 1);
    load_stage(2, 2);

    const int a_row = lane & 15;
    const int a_half = lane >> 4;
    const int b_nr = (lane & 7) + ((lane >> 4) << 3);
    const int b_half = (lane >> 3) & 1;

    int s = 0;       // stage of current chunk
    int fs = 2;      // stage freed at top of chunk c (valid for c>=1)
    for (int c = 0; c < N_CHUNK; c++) {
        if (c == 0)                 asm volatile("cp.async.wait_group 2;" ::: "memory");
        else if (c == N_CHUNK - 1)  asm volatile("cp.async.wait_group 0;" ::: "memory");
        else                        asm volatile("cp.async.wait_group 1;" ::: "memory");
        __syncthreads();   // all warps done with chunk c-1 -> stage fs free

        if (c >= 1 && c + 2 < N_CHUNK) load_stage(c + 2, fs);

        const uint32_t sA = sbase + s * STAGE_BYTES;
        const uint32_t sB = sA + TILE_B;

#pragma unroll
        for (int ks = 0; ks < 4; ks++) {
            uint32_t aa[4][4], bb[2][4];
#pragma unroll
            for (int mi = 0; mi < 4; mi++) {
                const uint32_t off = SWZ128(
                    (uint32_t)((wm * 64 + mi * 16 + a_row) * 128 + ks * 32 + a_half * 16));
                ldsm_x4(aa[mi], sA + off);
            }
#pragma unroll
            for (int j = 0; j < 2; j++) {
                const uint32_t off = SWZ128(
                    (uint32_t)((wn * 32 + j * 16 + b_nr) * 128 + ks * 32 + b_half * 16));
                ldsm_x4(bb[j], sB + off);
            }
#pragma unroll
            for (int mi = 0; mi < 4; mi++)
#pragma unroll
                for (int ni = 0; ni < 4; ni++)
                    mma16816(acc[mi][ni], aa[mi], &bb[ni >> 1][(ni & 1) * 2]);
        }
        fs = s;
        s = (s == N_STAGE - 1) ? 0 : s + 1;
    }

    // epilogue
#pragma unroll
    for (int mi = 0; mi < 4; mi++) {
        const int gm = m0 + wm * 64 + mi * 16 + (lane >> 2);
#pragma unroll
        for (int ni = 0; ni < 4; ni++) {
            const int gn = n0 + wn * 32 + ni * 8 + (lane & 3) * 2;
            float* p0 = C + (size_t)gm * D_SZ + gn;
            float* p1 = p0 + 8 * D_SZ;
            *(float2*)p0 = make_float2(acc[mi][ni][0], acc[mi][ni][1]);
            *(float2*)p1 = make_float2(acc[mi][ni][2], acc[mi][ni][3]);
        }
    }
}

// ---------------- split WKV scan (1 channel/thread, unroll 8) -----------------
__global__ void wkv_p1_kernel(const float* __restrict__ time_decay) {
    const int gid = blockIdx.x * blockDim.x + threadIdx.x;  // < N_SEG*CH_SZ
    const int c = gid & (CH_SZ - 1);
    const int seg = gid >> 14;
    const int d = c & (D_SZ - 1);
    const int b = c >> 11;
    const float w = expf(-expf(time_decay[d]));

    const size_t base = (size_t)b * T_SZ * D_SZ + (size_t)seg * SEG_LEN * D_SZ + d;
    const float* kp = g_k + base;
    const float* vp = g_v + base;

    float num = 0.f, den = 0.f;
    for (int t = 0; t < SEG_LEN; t += 8) {
        float kk[8], vv[8];
#pragma unroll
        for (int i = 0; i < 8; i++) {
            const size_t o = (size_t)(t + i) * D_SZ;
            kk[i] = kp[o]; vv[i] = vp[o];
        }
#pragma unroll
        for (int i = 0; i < 8; i++) {
            const float ek = expf(kk[i]);
            num = fmaf(w, num, ek * vv[i]);
            den = fmaf(w, den, ek);
        }
    }
    g_cn[gid] = num;
    g_cd[gid] = den;
}

__global__ void wkv_p2_kernel(const float* __restrict__ time_decay,
                              const float* __restrict__ x,
                              float* __restrict__ out) {
    const int gid = blockIdx.x * blockDim.x + threadIdx.x;
    const int c = gid & (CH_SZ - 1);
    const int seg = gid >> 14;
    const int d = c & (D_SZ - 1);
    const int b = c >> 11;

    const float e = expf(time_decay[d]);
    const float w = expf(-e);
    const float wl = expf(-(float)SEG_LEN * e);   // w^SEG_LEN

    float num = 0.f, den = 0.f;
    for (int i = 0; i < seg; i++) {
        num = fmaf(wl, num, g_cn[i * CH_SZ + c]);
        den = fmaf(wl, den, g_cd[i * CH_SZ + c]);
    }

    const size_t base = (size_t)b * T_SZ * D_SZ + (size_t)seg * SEG_LEN * D_SZ + d;
    const float* kp = g_k + base;
    const float* vp = g_v + base;
    const float* rp = g_r + base;
    float* op = out + base;

    for (int t = 0; t < SEG_LEN; t += 8) {
        float kk[8], vv[8], rr[8];
#pragma unroll
        for (int i = 0; i < 8; i++) {
            const size_t o = (size_t)(t + i) * D_SZ;
            kk[i] = kp[o]; vv[i] = vp[o]; rr[i] = rp[o];
        }
#pragma unroll
        for (int i = 0; i < 8; i++) {
            const float ek = expf(kk[i]);
            num = fmaf(w, num, ek * vv[i]);
            den = fmaf(w, den, ek);
            op[(size_t)(t + i) * D_SZ] = rr[i] * num / (den + 1e-8f);
        }
    }

    if (seg == 0) {
        float* out2 = out + (size_t)B_SZ * T_SZ * D_SZ;
        out2[c] = x[(size_t)b * T_SZ * D_SZ + (size_t)(T_SZ - 2) * D_SZ + d];
    }
}

// ---------------- launch --------------------------------------------------------
extern "C" void kernel_launch(void* const* d_in, const int* in_sizes, int n_in,
                              void* d_out, int out_size)
{
    const float* x  = (const float*)d_in[0];
    const float* Wk = (const float*)d_in[1];
    const float* Wv = (const float*)d_in[2];
    const float* Wr = (const float*)d_in[3];
    const float* td = (const float*)d_in[4];
    float* out = (float*)d_out;

    cudaFuncSetAttribute(gemm_hmma_kernel,
                         cudaFuncAttributeMaxDynamicSharedMemorySize, GEMM_SMEM);

    convert_x_kernel<<<(M_SZ * (size_t)D_SZ / 4 + 255) / 256, 256>>>(x);
    {
        dim3 g((D_SZ * (size_t)D_SZ / 4 + 255) / 256, 3);
        convert_w_kernel<<<g, 256>>>(Wk, Wv, Wr);
    }

    dim3 gg(D_SZ / BN, M_SZ / BM, 3);   // (16, 128, 3)
    gemm_hmma_kernel<<<gg, 256, GEMM_SMEM>>>();

    const int total = N_SEG * CH_SZ;    // 131072 threads
    wkv_p1_kernel<<<total / 256, 256>>>(td);
    wkv_p2_kernel<<<total / 256, 256>>>(td, x, out);
}

// round 9
// speedup vs baseline: 1.1015x; 1.0100x over previous
#include <cuda_runtime.h>
#include <cuda_fp16.h>
#include <cstdint>

// Problem constants (fixed: B=8, T=2048, D=2048)
#define B_SZ 8
#define T_SZ 2048
#define D_SZ 2048
#define M_SZ (B_SZ * T_SZ)        // 16384
#define CH_SZ (B_SZ * D_SZ)       // 16384 channels
#define SEG_LEN 256
#define N_SEG (T_SZ / SEG_LEN)    // 8

// ---------------- device scratch (static: no runtime allocation) ------------
__device__ __half g_xh[(size_t)M_SZ * D_SZ];     // fp16(x)
__device__ __half g_wh[(size_t)3 * D_SZ * D_SZ]; // fp16(W) for Wk,Wv,Wr
__device__ __half g_kh[(size_t)M_SZ * D_SZ];     // k (fp16)
__device__ __half g_vh[(size_t)M_SZ * D_SZ];     // v (fp16)
__device__ float g_r[(size_t)M_SZ * D_SZ];       // r (fp32)
__device__ float g_cn[(size_t)N_SEG * CH_SZ];
__device__ float g_cd[(size_t)N_SEG * CH_SZ];

// ---------------- helpers -----------------------------------------------------
__device__ __forceinline__ uint32_t smem_u32(const void* p) {
    uint32_t a;
    asm("{ .reg .u64 t; cvta.to.shared.u64 t, %1; cvt.u32.u64 %0, t; }" : "=r"(a) : "l"(p));
    return a;
}
__device__ __forceinline__ void cp16(uint32_t dst, const void* src) {
    asm volatile("cp.async.cg.shared.global [%0], [%1], 16;" :: "r"(dst), "l"(src));
}
// zfill variant: src_sz = 0 -> write 16 zero bytes
__device__ __forceinline__ void cp16z(uint32_t dst, const void* src, uint32_t src_sz) {
    asm volatile("cp.async.cg.shared.global [%0], [%1], 16, %2;"
                 :: "r"(dst), "l"(src), "r"(src_sz));
}
#define SWZ128(o) ((o) ^ (((o) >> 3) & 0x70))

__device__ __forceinline__ void ldsm_x4(uint32_t* r, uint32_t addr) {
    asm volatile("ldmatrix.sync.aligned.m8n8.x4.shared.b16 {%0,%1,%2,%3}, [%4];"
                 : "=r"(r[0]), "=r"(r[1]), "=r"(r[2]), "=r"(r[3]) : "r"(addr));
}
__device__ __forceinline__ void mma16816(float* c, const uint32_t* a, const uint32_t* b) {
    asm volatile(
        "mma.sync.aligned.m16n8k16.row.col.f32.f16.f16.f32 "
        "{%0,%1,%2,%3}, {%4,%5,%6,%7}, {%8,%9}, {%0,%1,%2,%3};"
        : "+f"(c[0]), "+f"(c[1]), "+f"(c[2]), "+f"(c[3])
        : "r"(a[0]), "r"(a[1]), "r"(a[2]), "r"(a[3]), "r"(b[0]), "r"(b[1]));
}

// ---------------- conversion: fp32 -> fp16 -------------------------------------
__global__ void convert_x_kernel(const float* __restrict__ x) {
    size_t i4 = (size_t)blockIdx.x * blockDim.x + threadIdx.x;
    if (i4 >= (size_t)M_SZ * D_SZ / 4) return;
    size_t i = i4 * 4;
    float4 v = *(const float4*)(x + i);
    __half2* hp = (__half2*)(g_xh + i);
    hp[0] = __halves2half2(__float2half_rn(v.x), __float2half_rn(v.y));
    hp[1] = __halves2half2(__float2half_rn(v.z), __float2half_rn(v.w));
}

__global__ void convert_w_kernel(const float* __restrict__ Wk,
                                 const float* __restrict__ Wv,
                                 const float* __restrict__ Wr) {
    const int z = blockIdx.y;
    const float* W = (z == 0) ? Wk : (z == 1) ? Wv : Wr;
    size_t i4 = (size_t)blockIdx.x * blockDim.x + threadIdx.x;
    if (i4 >= (size_t)D_SZ * D_SZ / 4) return;
    size_t i = i4 * 4;
    float4 v = *(const float4*)(W + i);
    __half2* op = (__half2*)(g_wh + (size_t)z * D_SZ * D_SZ + i);
    op[0] = __halves2half2(__float2half_rn(v.x), __float2half_rn(v.y));
    op[1] = __halves2half2(__float2half_rn(v.z), __float2half_rn(v.w));
}

// ---------------- HMMA GEMM: C[m,n] = sum_k A[m,k]*W[n,k] ---------------------
// Single fp16 MMA pass. Time shift read-side (zfill at t==0).
// Tile 128x128, BK=64, 3-stage cp.async, 2 CTA/SM, one sync per chunk.
// Output: z=0 -> g_kh (fp16), z=1 -> g_vh (fp16), z=2 -> g_r (fp32).
#define BM 128
#define BN 128
#define BK 64
#define N_CHUNK (D_SZ / BK)        // 32
#define TILE_B 16384               // 128 rows x 128B
#define STAGE_BYTES (2 * TILE_B)   // A, B
#define N_STAGE 3
#define GEMM_SMEM (N_STAGE * STAGE_BYTES)   // 96 KB

__global__ __launch_bounds__(256, 2)
void gemm_hmma_kernel() {
    extern __shared__ char smem[];
    const uint32_t sbase = smem_u32(smem);
    const int tid = threadIdx.x;
    const int wid = tid >> 5;
    const int lane = tid & 31;
    const int wm = wid & 1;          // 2 warps over M
    const int wn = wid >> 1;         // 4 warps over N

    const int z = blockIdx.z;
    const int m0 = blockIdx.y * BM;
    const int n0 = blockIdx.x * BN;
    const bool shift = (z < 2);

    const __half* B_h = g_wh + (size_t)z * D_SZ * D_SZ;

    float acc[4][4][4];
#pragma unroll
    for (int i = 0; i < 4; i++)
#pragma unroll
        for (int j = 0; j < 4; j++)
#pragma unroll
            for (int q = 0; q < 4; q++) acc[i][j][q] = 0.f;

    // stage loader: K-chunk c into stage s
    auto load_stage = [&](int c, int s) {
        const int kt = c * BK;
        const uint32_t st = sbase + s * STAGE_BYTES;
#pragma unroll
        for (int it = 0; it < 4; it++) {
            const int i = tid + it * 256;
            const int row = i >> 3, seg = i & 7;
            const uint32_t sw = SWZ128((uint32_t)(row * 128 + seg * 16));
            // A (time shift handled here; zero row at t==0)
            const int rm = m0 + row;
            uint32_t sz = 16;
            int srow = rm;
            if (shift) {
                if ((rm & (T_SZ - 1)) == 0) sz = 0;
                else srow = rm - 1;
            }
            cp16z(st + sw, g_xh + (size_t)srow * D_SZ + kt + seg * 8, sz);
            // B
            cp16(st + TILE_B + sw, B_h + (size_t)(n0 + row) * D_SZ + kt + seg * 8);
        }
        asm volatile("cp.async.commit_group;" ::: "memory");
    };

    load_stage(0, 0);
    load_stage(1, 1);
    load_stage(2, 2);

    const int a_row = lane & 15;
    const int a_half = lane >> 4;
    const int b_nr = (lane & 7) + ((lane >> 4) << 3);
    const int b_half = (lane >> 3) & 1;

    int s = 0;       // stage of current chunk
    int fs = 2;      // stage freed at top of chunk c (valid for c>=1)
    for (int c = 0; c < N_CHUNK; c++) {
        if (c == 0)                 asm volatile("cp.async.wait_group 2;" ::: "memory");
        else if (c == N_CHUNK - 1)  asm volatile("cp.async.wait_group 0;" ::: "memory");
        else                        asm volatile("cp.async.wait_group 1;" ::: "memory");
        __syncthreads();   // all warps done with chunk c-1 -> stage fs free

        if (c >= 1 && c + 2 < N_CHUNK) load_stage(c + 2, fs);

        const uint32_t sA = sbase + s * STAGE_BYTES;
        const uint32_t sB = sA + TILE_B;

#pragma unroll
        for (int ks = 0; ks < 4; ks++) {
            uint32_t aa[4][4], bb[2][4];
#pragma unroll
            for (int mi = 0; mi < 4; mi++) {
                const uint32_t off = SWZ128(
                    (uint32_t)((wm * 64 + mi * 16 + a_row) * 128 + ks * 32 + a_half * 16));
                ldsm_x4(aa[mi], sA + off);
            }
#pragma unroll
            for (int j = 0; j < 2; j++) {
                const uint32_t off = SWZ128(
                    (uint32_t)((wn * 32 + j * 16 + b_nr) * 128 + ks * 32 + b_half * 16));
                ldsm_x4(bb[j], sB + off);
            }
#pragma unroll
            for (int mi = 0; mi < 4; mi++)
#pragma unroll
                for (int ni = 0; ni < 4; ni++)
                    mma16816(acc[mi][ni], aa[mi], &bb[ni >> 1][(ni & 1) * 2]);
        }
        fs = s;
        s = (s == N_STAGE - 1) ? 0 : s + 1;
    }

    // epilogue: k,v -> fp16; r -> fp32
    if (z == 2) {
#pragma unroll
        for (int mi = 0; mi < 4; mi++) {
            const int gm = m0 + wm * 64 + mi * 16 + (lane >> 2);
#pragma unroll
            for (int ni = 0; ni < 4; ni++) {
                const int gn = n0 + wn * 32 + ni * 8 + (lane & 3) * 2;
                float* p0 = g_r + (size_t)gm * D_SZ + gn;
                float* p1 = p0 + 8 * D_SZ;
                *(float2*)p0 = make_float2(acc[mi][ni][0], acc[mi][ni][1]);
                *(float2*)p1 = make_float2(acc[mi][ni][2], acc[mi][ni][3]);
            }
        }
    } else {
        __half* Ch = (z == 0) ? g_kh : g_vh;
#pragma unroll
        for (int mi = 0; mi < 4; mi++) {
            const int gm = m0 + wm * 64 + mi * 16 + (lane >> 2);
#pragma unroll
            for (int ni = 0; ni < 4; ni++) {
                const int gn = n0 + wn * 32 + ni * 8 + (lane & 3) * 2;
                __half* p0 = Ch + (size_t)gm * D_SZ + gn;
                __half* p1 = p0 + 8 * D_SZ;
                *(__half2*)p0 = __halves2half2(__float2half_rn(acc[mi][ni][0]),
                                               __float2half_rn(acc[mi][ni][1]));
                *(__half2*)p1 = __halves2half2(__float2half_rn(acc[mi][ni][2]),
                                               __float2half_rn(acc[mi][ni][3]));
            }
        }
    }
}

// ---------------- split WKV scan (1 channel/thread, unroll 8) -----------------
__global__ void wkv_p1_kernel(const float* __restrict__ time_decay) {
    const int gid = blockIdx.x * blockDim.x + threadIdx.x;  // < N_SEG*CH_SZ
    const int c = gid & (CH_SZ - 1);
    const int seg = gid >> 14;
    const int d = c & (D_SZ - 1);
    const int b = c >> 11;
    const float w = expf(-expf(time_decay[d]));

    const size_t base = (size_t)b * T_SZ * D_SZ + (size_t)seg * SEG_LEN * D_SZ + d;
    const __half* kp = g_kh + base;
    const __half* vp = g_vh + base;

    float num = 0.f, den = 0.f;
    for (int t = 0; t < SEG_LEN; t += 8) {
        float kk[8], vv[8];
#pragma unroll
        for (int i = 0; i < 8; i++) {
            const size_t o = (size_t)(t + i) * D_SZ;
            kk[i] = __half2float(kp[o]); vv[i] = __half2float(vp[o]);
        }
#pragma unroll
        for (int i = 0; i < 8; i++) {
            const float ek = expf(kk[i]);
            num = fmaf(w, num, ek * vv[i]);
            den = fmaf(w, den, ek);
        }
    }
    g_cn[gid] = num;
    g_cd[gid] = den;
}

__global__ void wkv_p2_kernel(const float* __restrict__ time_decay,
                              const float* __restrict__ x,
                              float* __restrict__ out) {
    const int gid = blockIdx.x * blockDim.x + threadIdx.x;
    const int c = gid & (CH_SZ - 1);
    const int seg = gid >> 14;
    const int d = c & (D_SZ - 1);
    const int b = c >> 11;

    const float e = expf(time_decay[d]);
    const float w = expf(-e);
    const float wl = expf(-(float)SEG_LEN * e);   // w^SEG_LEN

    float num = 0.f, den = 0.f;
    for (int i = 0; i < seg; i++) {
        num = fmaf(wl, num, g_cn[i * CH_SZ + c]);
        den = fmaf(wl, den, g_cd[i * CH_SZ + c]);
    }

    const size_t base = (size_t)b * T_SZ * D_SZ + (size_t)seg * SEG_LEN * D_SZ + d;
    const __half* kp = g_kh + base;
    const __half* vp = g_vh + base;
    const float* rp = g_r + base;
    float* op = out + base;

    for (int t = 0; t < SEG_LEN; t += 8) {
        float kk[8], vv[8], rr[8];
#pragma unroll
        for (int i = 0; i < 8; i++) {
            const size_t o = (size_t)(t + i) * D_SZ;
            kk[i] = __half2float(kp[o]); vv[i] = __half2float(vp[o]); rr[i] = rp[o];
        }
#pragma unroll
        for (int i = 0; i < 8; i++) {
            const float ek = expf(kk[i]);
            num = fmaf(w, num, ek * vv[i]);
            den = fmaf(w, den, ek);
            op[(size_t)(t + i) * D_SZ] = rr[i] * num / (den + 1e-8f);
        }
    }

    if (seg == 0) {
        float* out2 = out + (size_t)B_SZ * T_SZ * D_SZ;
        out2[c] = x[(size_t)b * T_SZ * D_SZ + (size_t)(T_SZ - 2) * D_SZ + d];
    }
}

// ---------------- launch --------------------------------------------------------
extern "C" void kernel_launch(void* const* d_in, const int* in_sizes, int n_in,
                              void* d_out, int out_size)
{
    const float* x  = (const float*)d_in[0];
    const float* Wk = (const float*)d_in[1];
    const float* Wv = (const float*)d_in[2];
    const float* Wr = (const float*)d_in[3];
    const float* td = (const float*)d_in[4];
    float* out = (float*)d_out;

    cudaFuncSetAttribute(gemm_hmma_kernel,
                         cudaFuncAttributeMaxDynamicSharedMemorySize, GEMM_SMEM);

    convert_x_kernel<<<(M_SZ * (size_t)D_SZ / 4 + 255) / 256, 256>>>(x);
    {
        dim3 g((D_SZ * (size_t)D_SZ / 4 + 255) / 256, 3);
        convert_w_kernel<<<g, 256>>>(Wk, Wv, Wr);
    }

    dim3 gg(D_SZ / BN, M_SZ / BM, 3);   // (16, 128, 3)
    gemm_hmma_kernel<<<gg, 256, GEMM_SMEM>>>();

    const int total = N_SEG * CH_SZ;    // 131072 threads
    wkv_p1_kernel<<<total / 256, 256>>>(td);
    wkv_p2_kernel<<<total / 256, 256>>>(td, x, out);
}

// round 10
// speedup vs baseline: 1.1053x; 1.0035x over previous
#include <cuda_runtime.h>
#include <cuda_fp16.h>
#include <cstdint>

// Problem constants (fixed: B=8, T=2048, D=2048)
#define B_SZ 8
#define T_SZ 2048
#define D_SZ 2048
#define M_SZ (B_SZ * T_SZ)        // 16384
#define CH_SZ (B_SZ * D_SZ)       // 16384 channels
#define SEG_LEN 128
#define N_SEG (T_SZ / SEG_LEN)    // 16

// ---------------- device scratch (static: no runtime allocation) ------------
__device__ __half g_xh[(size_t)M_SZ * D_SZ];     // fp16(x)
__device__ __half g_wh[(size_t)3 * D_SZ * D_SZ]; // fp16(W) for Wk,Wv,Wr
__device__ __half g_kh[(size_t)M_SZ * D_SZ];     // k (fp16)
__device__ __half g_vh[(size_t)M_SZ * D_SZ];     // v (fp16)
__device__ float g_r[(size_t)M_SZ * D_SZ];       // r (fp32)
__device__ float g_cn[(size_t)N_SEG * CH_SZ];
__device__ float g_cd[(size_t)N_SEG * CH_SZ];

// ---------------- helpers -----------------------------------------------------
__device__ __forceinline__ uint32_t smem_u32(const void* p) {
    uint32_t a;
    asm("{ .reg .u64 t; cvta.to.shared.u64 t, %1; cvt.u32.u64 %0, t; }" : "=r"(a) : "l"(p));
    return a;
}
__device__ __forceinline__ void cp16(uint32_t dst, const void* src) {
    asm volatile("cp.async.cg.shared.global [%0], [%1], 16;" :: "r"(dst), "l"(src));
}
// zfill variant: src_sz = 0 -> write 16 zero bytes
__device__ __forceinline__ void cp16z(uint32_t dst, const void* src, uint32_t src_sz) {
    asm volatile("cp.async.cg.shared.global [%0], [%1], 16, %2;"
                 :: "r"(dst), "l"(src), "r"(src_sz));
}
#define SWZ128(o) ((o) ^ (((o) >> 3) & 0x70))

__device__ __forceinline__ void ldsm_x4(uint32_t* r, uint32_t addr) {
    asm volatile("ldmatrix.sync.aligned.m8n8.x4.shared.b16 {%0,%1,%2,%3}, [%4];"
                 : "=r"(r[0]), "=r"(r[1]), "=r"(r[2]), "=r"(r[3]) : "r"(addr));
}
__device__ __forceinline__ void mma16816(float* c, const uint32_t* a, const uint32_t* b) {
    asm volatile(
        "mma.sync.aligned.m16n8k16.row.col.f32.f16.f16.f32 "
        "{%0,%1,%2,%3}, {%4,%5,%6,%7}, {%8,%9}, {%0,%1,%2,%3};"
        : "+f"(c[0]), "+f"(c[1]), "+f"(c[2]), "+f"(c[3])
        : "r"(a[0]), "r"(a[1]), "r"(a[2]), "r"(a[3]), "r"(b[0]), "r"(b[1]));
}

// ---------------- fused conversion: fp32 -> fp16 (x and all 3 W) ---------------
#define X_QUADS ((size_t)M_SZ * D_SZ / 4)          // 8388608
#define W_QUADS ((size_t)3 * D_SZ * D_SZ / 4)      // 3145728
#define CV_TOTAL (X_QUADS + W_QUADS)

__global__ void convert_all_kernel(const float* __restrict__ x,
                                   const float* __restrict__ Wk,
                                   const float* __restrict__ Wv,
                                   const float* __restrict__ Wr) {
    size_t q = (size_t)blockIdx.x * blockDim.x + threadIdx.x;
    if (q >= CV_TOTAL) return;
    const float* src;
    __half* dst;
    size_t i;
    if (q < X_QUADS) {
        i = q * 4;
        src = x;
        dst = g_xh;
    } else {
        size_t wq = q - X_QUADS;
        const size_t wsz = (size_t)D_SZ * D_SZ;   // elems per W
        size_t z = wq / (wsz / 4);
        i = (wq - z * (wsz / 4)) * 4;
        src = (z == 0) ? Wk : (z == 1) ? Wv : Wr;
        dst = g_wh + z * wsz;
    }
    float4 v = *(const float4*)(src + i);
    __half2* op = (__half2*)(dst + i);
    op[0] = __halves2half2(__float2half_rn(v.x), __float2half_rn(v.y));
    op[1] = __halves2half2(__float2half_rn(v.z), __float2half_rn(v.w));
}

// ---------------- HMMA GEMM: C[m,n] = sum_k A[m,k]*W[n,k] ---------------------
// Single fp16 MMA pass. Time shift read-side (zfill at t==0).
// Tile 128x128, BK=64, 3-stage cp.async, 2 CTA/SM, one sync per chunk.
// Output: z=0 -> g_kh (fp16), z=1 -> g_vh (fp16), z=2 -> g_r (fp32).
#define BM 128
#define BN 128
#define BK 64
#define N_CHUNK (D_SZ / BK)        // 32
#define TILE_B 16384               // 128 rows x 128B
#define STAGE_BYTES (2 * TILE_B)   // A, B
#define N_STAGE 3
#define GEMM_SMEM (N_STAGE * STAGE_BYTES)   // 96 KB

__global__ __launch_bounds__(256, 2)
void gemm_hmma_kernel() {
    extern __shared__ char smem[];
    const uint32_t sbase = smem_u32(smem);
    const int tid = threadIdx.x;
    const int wid = tid >> 5;
    const int lane = tid & 31;
    const int wm = wid & 1;          // 2 warps over M
    const int wn = wid >> 1;         // 4 warps over N

    const int z = blockIdx.z;
    const int m0 = blockIdx.y * BM;
    const int n0 = blockIdx.x * BN;
    const bool shift = (z < 2);

    const __half* B_h = g_wh + (size_t)z * D_SZ * D_SZ;

    float acc[4][4][4];
#pragma unroll
    for (int i = 0; i < 4; i++)
#pragma unroll
        for (int j = 0; j < 4; j++)
#pragma unroll
            for (int q = 0; q < 4; q++) acc[i][j][q] = 0.f;

    // stage loader: K-chunk c into stage s
    auto load_stage = [&](int c, int s) {
        const int kt = c * BK;
        const uint32_t st = sbase + s * STAGE_BYTES;
#pragma unroll
        for (int it = 0; it < 4; it++) {
            const int i = tid + it * 256;
            const int row = i >> 3, seg = i & 7;
            const uint32_t sw = SWZ128((uint32_t)(row * 128 + seg * 16));
            // A (time shift handled here; zero row at t==0)
            const int rm = m0 + row;
            uint32_t sz = 16;
            int srow = rm;
            if (shift) {
                if ((rm & (T_SZ - 1)) == 0) sz = 0;
                else srow = rm - 1;
            }
            cp16z(st + sw, g_xh + (size_t)srow * D_SZ + kt + seg * 8, sz);
            // B
            cp16(st + TILE_B + sw, B_h + (size_t)(n0 + row) * D_SZ + kt + seg * 8);
        }
        asm volatile("cp.async.commit_group;" ::: "memory");
    };

    load_stage(0, 0);
    load_stage(1, 1);
    load_stage(2, 2);

    const int a_row = lane & 15;
    const int a_half = lane >> 4;
    const int b_nr = (lane & 7) + ((lane >> 4) << 3);
    const int b_half = (lane >> 3) & 1;

    int s = 0;       // stage of current chunk
    int fs = 2;      // stage freed at top of chunk c (valid for c>=1)
    for (int c = 0; c < N_CHUNK; c++) {
        if (c == 0)                 asm volatile("cp.async.wait_group 2;" ::: "memory");
        else if (c == N_CHUNK - 1)  asm volatile("cp.async.wait_group 0;" ::: "memory");
        else                        asm volatile("cp.async.wait_group 1;" ::: "memory");
        __syncthreads();   // all warps done with chunk c-1 -> stage fs free

        if (c >= 1 && c + 2 < N_CHUNK) load_stage(c + 2, fs);

        const uint32_t sA = sbase + s * STAGE_BYTES;
        const uint32_t sB = sA + TILE_B;

#pragma unroll
        for (int ks = 0; ks < 4; ks++) {
            uint32_t aa[4][4], bb[2][4];
#pragma unroll
            for (int mi = 0; mi < 4; mi++) {
                const uint32_t off = SWZ128(
                    (uint32_t)((wm * 64 + mi * 16 + a_row) * 128 + ks * 32 + a_half * 16));
                ldsm_x4(aa[mi], sA + off);
            }
#pragma unroll
            for (int j = 0; j < 2; j++) {
                const uint32_t off = SWZ128(
                    (uint32_t)((wn * 32 + j * 16 + b_nr) * 128 + ks * 32 + b_half * 16));
                ldsm_x4(bb[j], sB + off);
            }
#pragma unroll
            for (int mi = 0; mi < 4; mi++)
#pragma unroll
                for (int ni = 0; ni < 4; ni++)
                    mma16816(acc[mi][ni], aa[mi], &bb[ni >> 1][(ni & 1) * 2]);
        }
        fs = s;
        s = (s == N_STAGE - 1) ? 0 : s + 1;
    }

    // epilogue: k,v -> fp16; r -> fp32
    if (z == 2) {
#pragma unroll
        for (int mi = 0; mi < 4; mi++) {
            const int gm = m0 + wm * 64 + mi * 16 + (lane >> 2);
#pragma unroll
            for (int ni = 0; ni < 4; ni++) {
                const int gn = n0 + wn * 32 + ni * 8 + (lane & 3) * 2;
                float* p0 = g_r + (size_t)gm * D_SZ + gn;
                float* p1 = p0 + 8 * D_SZ;
                *(float2*)p0 = make_float2(acc[mi][ni][0], acc[mi][ni][1]);
                *(float2*)p1 = make_float2(acc[mi][ni][2], acc[mi][ni][3]);
            }
        }
    } else {
        __half* Ch = (z == 0) ? g_kh : g_vh;
#pragma unroll
        for (int mi = 0; mi < 4; mi++) {
            const int gm = m0 + wm * 64 + mi * 16 + (lane >> 2);
#pragma unroll
            for (int ni = 0; ni < 4; ni++) {
                const int gn = n0 + wn * 32 + ni * 8 + (lane & 3) * 2;
                __half* p0 = Ch + (size_t)gm * D_SZ + gn;
                __half* p1 = p0 + 8 * D_SZ;
                *(__half2*)p0 = __halves2half2(__float2half_rn(acc[mi][ni][0]),
                                               __float2half_rn(acc[mi][ni][1]));
                *(__half2*)p1 = __halves2half2(__float2half_rn(acc[mi][ni][2]),
                                               __float2half_rn(acc[mi][ni][3]));
            }
        }
    }
}

// ---------------- split WKV scan (1 channel/thread, 16 segments) --------------
__global__ void wkv_p1_kernel(const float* __restrict__ time_decay) {
    const int gid = blockIdx.x * blockDim.x + threadIdx.x;  // < N_SEG*CH_SZ
    const int c = gid & (CH_SZ - 1);
    const int seg = gid >> 14;
    const int d = c & (D_SZ - 1);
    const int b = c >> 11;
    const float w = expf(-expf(time_decay[d]));

    const size_t base = (size_t)b * T_SZ * D_SZ + (size_t)seg * SEG_LEN * D_SZ + d;
    const __half* kp = g_kh + base;
    const __half* vp = g_vh + base;

    float num = 0.f, den = 0.f;
    for (int t = 0; t < SEG_LEN; t += 8) {
        float kk[8], vv[8];
#pragma unroll
        for (int i = 0; i < 8; i++) {
            const size_t o = (size_t)(t + i) * D_SZ;
            kk[i] = __half2float(kp[o]); vv[i] = __half2float(vp[o]);
        }
#pragma unroll
        for (int i = 0; i < 8; i++) {
            const float ek = expf(kk[i]);
            num = fmaf(w, num, ek * vv[i]);
            den = fmaf(w, den, ek);
        }
    }
    g_cn[gid] = num;
    g_cd[gid] = den;
}

__global__ void wkv_p2_kernel(const float* __restrict__ time_decay,
                              const float* __restrict__ x,
                              float* __restrict__ out) {
    const int gid = blockIdx.x * blockDim.x + threadIdx.x;
    const int c = gid & (CH_SZ - 1);
    const int seg = gid >> 14;
    const int d = c & (D_SZ - 1);
    const int b = c >> 11;

    const float e = expf(time_decay[d]);
    const float w = expf(-e);
    const float wl = expf(-(float)SEG_LEN * e);   // w^SEG_LEN

    float num = 0.f, den = 0.f;
    for (int i = 0; i < seg; i++) {
        num = fmaf(wl, num, g_cn[i * CH_SZ + c]);
        den = fmaf(wl, den, g_cd[i * CH_SZ + c]);
    }

    const size_t base = (size_t)b * T_SZ * D_SZ + (size_t)seg * SEG_LEN * D_SZ + d;
    const __half* kp = g_kh + base;
    const __half* vp = g_vh + base;
    const float* rp = g_r + base;
    float* op = out + base;

    for (int t = 0; t < SEG_LEN; t += 8) {
        float kk[8], vv[8], rr[8];
#pragma unroll
        for (int i = 0; i < 8; i++) {
            const size_t o = (size_t)(t + i) * D_SZ;
            kk[i] = __half2float(kp[o]); vv[i] = __half2float(vp[o]); rr[i] = rp[o];
        }
#pragma unroll
        for (int i = 0; i < 8; i++) {
            const float ek = expf(kk[i]);
            num = fmaf(w, num, ek * vv[i]);
            den = fmaf(w, den, ek);
            op[(size_t)(t + i) * D_SZ] = rr[i] * num / (den + 1e-8f);
        }
    }

    if (seg == 0) {
        float* out2 = out + (size_t)B_SZ * T_SZ * D_SZ;
        out2[c] = x[(size_t)b * T_SZ * D_SZ + (size_t)(T_SZ - 2) * D_SZ + d];
    }
}

// ---------------- launch --------------------------------------------------------
extern "C" void kernel_launch(void* const* d_in, const int* in_sizes, int n_in,
                              void* d_out, int out_size)
{
    const float* x  = (const float*)d_in[0];
    const float* Wk = (const float*)d_in[1];
    const float* Wv = (const float*)d_in[2];
    const float* Wr = (const float*)d_in[3];
    const float* td = (const float*)d_in[4];
    float* out = (float*)d_out;

    cudaFuncSetAttribute(gemm_hmma_kernel,
                         cudaFuncAttributeMaxDynamicSharedMemorySize, GEMM_SMEM);

    convert_all_kernel<<<(unsigned)((CV_TOTAL + 255) / 256), 256>>>(x, Wk, Wv, Wr);

    dim3 gg(D_SZ / BN, M_SZ / BM, 3);   // (16, 128, 3)
    gemm_hmma_kernel<<<gg, 256, GEMM_SMEM>>>();

    const int total = N_SEG * CH_SZ;    // 262144 threads
    wkv_p1_kernel<<<total / 256, 256>>>(td);
    wkv_p2_kernel<<<total / 256, 256>>>(td, x, out);
}

// round 11
// speedup vs baseline: 1.1296x; 1.0220x over previous
#include <cuda_runtime.h>
#include <cuda_fp16.h>
#include <cstdint>

// Problem constants (fixed: B=8, T=2048, D=2048)
#define B_SZ 8
#define T_SZ 2048
#define D_SZ 2048
#define M_SZ (B_SZ * T_SZ)        // 16384
#define CH_SZ (B_SZ * D_SZ)       // 16384 channels
#define SEG_LEN 128
#define N_SEG (T_SZ / SEG_LEN)    // 16

// ---------------- device scratch (static: no runtime allocation) ------------
__device__ __half g_xh[(size_t)M_SZ * D_SZ];     // fp16(x)
__device__ __half g_wh[(size_t)3 * D_SZ * D_SZ]; // fp16(W) for Wk,Wv,Wr
__device__ __half g_kh[(size_t)M_SZ * D_SZ];     // k (fp16)
__device__ __half g_vh[(size_t)M_SZ * D_SZ];     // v (fp16)
__device__ __half g_rh[(size_t)M_SZ * D_SZ];     // r (fp16)
__device__ float g_cn[(size_t)N_SEG * CH_SZ];
__device__ float g_cd[(size_t)N_SEG * CH_SZ];

// ---------------- helpers -----------------------------------------------------
__device__ __forceinline__ uint32_t smem_u32(const void* p) {
    uint32_t a;
    asm("{ .reg .u64 t; cvta.to.shared.u64 t, %1; cvt.u32.u64 %0, t; }" : "=r"(a) : "l"(p));
    return a;
}
__device__ __forceinline__ void cp16(uint32_t dst, const void* src) {
    asm volatile("cp.async.cg.shared.global [%0], [%1], 16;" :: "r"(dst), "l"(src));
}
// zfill variant: src_sz = 0 -> write 16 zero bytes
__device__ __forceinline__ void cp16z(uint32_t dst, const void* src, uint32_t src_sz) {
    asm volatile("cp.async.cg.shared.global [%0], [%1], 16, %2;"
                 :: "r"(dst), "l"(src), "r"(src_sz));
}
#define SWZ128(o) ((o) ^ (((o) >> 3) & 0x70))

__device__ __forceinline__ void ldsm_x4(uint32_t* r, uint32_t addr) {
    asm volatile("ldmatrix.sync.aligned.m8n8.x4.shared.b16 {%0,%1,%2,%3}, [%4];"
                 : "=r"(r[0]), "=r"(r[1]), "=r"(r[2]), "=r"(r[3]) : "r"(addr));
}
__device__ __forceinline__ void mma16816(float* c, const uint32_t* a, const uint32_t* b) {
    asm volatile(
        "mma.sync.aligned.m16n8k16.row.col.f32.f16.f16.f32 "
        "{%0,%1,%2,%3}, {%4,%5,%6,%7}, {%8,%9}, {%0,%1,%2,%3};"
        : "+f"(c[0]), "+f"(c[1]), "+f"(c[2]), "+f"(c[3])
        : "r"(a[0]), "r"(a[1]), "r"(a[2]), "r"(a[3]), "r"(b[0]), "r"(b[1]));
}

// ---------------- fused conversion: fp32 -> fp16 (x and all 3 W) ---------------
// 8 elements per thread (2 x float4).
#define X_OCT ((size_t)M_SZ * D_SZ / 8)          // 4194304
#define W_OCT ((size_t)3 * D_SZ * D_SZ / 8)      // 1572864
#define CV_TOTAL (X_OCT + W_OCT)

__global__ void convert_all_kernel(const float* __restrict__ x,
                                   const float* __restrict__ Wk,
                                   const float* __restrict__ Wv,
                                   const float* __restrict__ Wr) {
    size_t q = (size_t)blockIdx.x * blockDim.x + threadIdx.x;
    if (q >= CV_TOTAL) return;
    const float* src;
    __half* dst;
    size_t i;
    if (q < X_OCT) {
        i = q * 8;
        src = x;
        dst = g_xh;
    } else {
        size_t wq = q - X_OCT;
        const size_t wsz = (size_t)D_SZ * D_SZ;   // elems per W
        size_t z = wq / (wsz / 8);
        i = (wq - z * (wsz / 8)) * 8;
        src = (z == 0) ? Wk : (z == 1) ? Wv : Wr;
        dst = g_wh + z * wsz;
    }
    float4 v0 = *(const float4*)(src + i);
    float4 v1 = *(const float4*)(src + i + 4);
    __half2* op = (__half2*)(dst + i);
    op[0] = __halves2half2(__float2half_rn(v0.x), __float2half_rn(v0.y));
    op[1] = __halves2half2(__float2half_rn(v0.z), __float2half_rn(v0.w));
    op[2] = __halves2half2(__float2half_rn(v1.x), __float2half_rn(v1.y));
    op[3] = __halves2half2(__float2half_rn(v1.z), __float2half_rn(v1.w));
}

// ---------------- HMMA GEMM: C[m,n] = sum_k A[m,k]*W[n,k] ---------------------
// Single fp16 MMA pass. Time shift read-side (zfill at t==0).
// Tile 128x128, BK=64, 3-stage cp.async, 2 CTA/SM, one sync per chunk.
// Output: z=0 -> g_kh, z=1 -> g_vh, z=2 -> g_rh (all fp16).
#define BM 128
#define BN 128
#define BK 64
#define N_CHUNK (D_SZ / BK)        // 32
#define TILE_B 16384               // 128 rows x 128B
#define STAGE_BYTES (2 * TILE_B)   // A, B
#define N_STAGE 3
#define GEMM_SMEM (N_STAGE * STAGE_BYTES)   // 96 KB

__global__ __launch_bounds__(256, 2)
void gemm_hmma_kernel() {
    extern __shared__ char smem[];
    const uint32_t sbase = smem_u32(smem);
    const int tid = threadIdx.x;
    const int wid = tid >> 5;
    const int lane = tid & 31;
    const int wm = wid & 1;          // 2 warps over M
    const int wn = wid >> 1;         // 4 warps over N

    const int z = blockIdx.z;
    const int m0 = blockIdx.y * BM;
    const int n0 = blockIdx.x * BN;
    const bool shift = (z < 2);

    const __half* B_h = g_wh + (size_t)z * D_SZ * D_SZ;
    __half* Ch = (z == 0) ? g_kh : (z == 1) ? g_vh : g_rh;

    float acc[4][4][4];
#pragma unroll
    for (int i = 0; i < 4; i++)
#pragma unroll
        for (int j = 0; j < 4; j++)
#pragma unroll
            for (int q = 0; q < 4; q++) acc[i][j][q] = 0.f;

    // stage loader: K-chunk c into stage s
    auto load_stage = [&](int c, int s) {
        const int kt = c * BK;
        const uint32_t st = sbase + s * STAGE_BYTES;
#pragma unroll
        for (int it = 0; it < 4; it++) {
            const int i = tid + it * 256;
            const int row = i >> 3, seg = i & 7;
            const uint32_t sw = SWZ128((uint32_t)(row * 128 + seg * 16));
            // A (time shift handled here; zero row at t==0)
            const int rm = m0 + row;
            uint32_t sz = 16;
            int srow = rm;
            if (shift) {
                if ((rm & (T_SZ - 1)) == 0) sz = 0;
                else srow = rm - 1;
            }
            cp16z(st + sw, g_xh + (size_t)srow * D_SZ + kt + seg * 8, sz);
            // B
            cp16(st + TILE_B + sw, B_h + (size_t)(n0 + row) * D_SZ + kt + seg * 8);
        }
        asm volatile("cp.async.commit_group;" ::: "memory");
    };

    load_stage(0, 0);
    load_stage(1, 1);
    load_stage(2, 2);

    const int a_row = lane & 15;
    const int a_half = lane >> 4;
    const int b_nr = (lane & 7) + ((lane >> 4) << 3);
    const int b_half = (lane >> 3) & 1;

    int s = 0;       // stage of current chunk
    int fs = 2;      // stage freed at top of chunk c (valid for c>=1)
    for (int c = 0; c < N_CHUNK; c++) {
        if (c == 0)                 asm volatile("cp.async.wait_group 2;" ::: "memory");
        else if (c == N_CHUNK - 1)  asm volatile("cp.async.wait_group 0;" ::: "memory");
        else                        asm volatile("cp.async.wait_group 1;" ::: "memory");
        __syncthreads();   // all warps done with chunk c-1 -> stage fs free

        if (c >= 1 && c + 2 < N_CHUNK) load_stage(c + 2, fs);

        const uint32_t sA = sbase + s * STAGE_BYTES;
        const uint32_t sB = sA + TILE_B;

#pragma unroll
        for (int ks = 0; ks < 4; ks++) {
            uint32_t aa[4][4], bb[2][4];
#pragma unroll
            for (int mi = 0; mi < 4; mi++) {
                const uint32_t off = SWZ128(
                    (uint32_t)((wm * 64 + mi * 16 + a_row) * 128 + ks * 32 + a_half * 16));
                ldsm_x4(aa[mi], sA + off);
            }
#pragma unroll
            for (int j = 0; j < 2; j++) {
                const uint32_t off = SWZ128(
                    (uint32_t)((wn * 32 + j * 16 + b_nr) * 128 + ks * 32 + b_half * 16));
                ldsm_x4(bb[j], sB + off);
            }
#pragma unroll
            for (int mi = 0; mi < 4; mi++)
#pragma unroll
                for (int ni = 0; ni < 4; ni++)
                    mma16816(acc[mi][ni], aa[mi], &bb[ni >> 1][(ni & 1) * 2]);
        }
        fs = s;
        s = (s == N_STAGE - 1) ? 0 : s + 1;
    }

    // epilogue: all outputs fp16
#pragma unroll
    for (int mi = 0; mi < 4; mi++) {
        const int gm = m0 + wm * 64 + mi * 16 + (lane >> 2);
#pragma unroll
        for (int ni = 0; ni < 4; ni++) {
            const int gn = n0 + wn * 32 + ni * 8 + (lane & 3) * 2;
            __half* p0 = Ch + (size_t)gm * D_SZ + gn;
            __half* p1 = p0 + 8 * D_SZ;
            *(__half2*)p0 = __halves2half2(__float2half_rn(acc[mi][ni][0]),
                                           __float2half_rn(acc[mi][ni][1]));
            *(__half2*)p1 = __halves2half2(__float2half_rn(acc[mi][ni][2]),
                                           __float2half_rn(acc[mi][ni][3]));
        }
    }
}

// ---------------- split WKV scan (1 channel/thread, 16 segments) --------------
// p1: carries for segments 0..N_SEG-2 only (last segment's carry is unused).
__global__ void wkv_p1_kernel(const float* __restrict__ time_decay) {
    const int gid = blockIdx.x * blockDim.x + threadIdx.x;  // < (N_SEG-1)*CH_SZ
    const int c = gid & (CH_SZ - 1);
    const int seg = gid >> 14;
    const int d = c & (D_SZ - 1);
    const int b = c >> 11;
    const float w = expf(-expf(time_decay[d]));

    const size_t base = (size_t)b * T_SZ * D_SZ + (size_t)seg * SEG_LEN * D_SZ + d;
    const __half* kp = g_kh + base;
    const __half* vp = g_vh + base;

    float num = 0.f, den = 0.f;
    for (int t = 0; t < SEG_LEN; t += 8) {
        float kk[8], vv[8];
#pragma unroll
        for (int i = 0; i < 8; i++) {
            const size_t o = (size_t)(t + i) * D_SZ;
            kk[i] = __half2float(kp[o]); vv[i] = __half2float(vp[o]);
        }
#pragma unroll
        for (int i = 0; i < 8; i++) {
            const float ek = expf(kk[i]);
            num = fmaf(w, num, ek * vv[i]);
            den = fmaf(w, den, ek);
        }
    }
    g_cn[gid] = num;
    g_cd[gid] = den;
}

__global__ void wkv_p2_kernel(const float* __restrict__ time_decay,
                              const float* __restrict__ x,
                              float* __restrict__ out) {
    const int gid = blockIdx.x * blockDim.x + threadIdx.x;
    const int c = gid & (CH_SZ - 1);
    const int seg = gid >> 14;
    const int d = c & (D_SZ - 1);
    const int b = c >> 11;

    const float e = expf(time_decay[d]);
    const float w = expf(-e);
    const float wl = expf(-(float)SEG_LEN * e);   // w^SEG_LEN

    float num = 0.f, den = 0.f;
    for (int i = 0; i < seg; i++) {
        num = fmaf(wl, num, g_cn[i * CH_SZ + c]);
        den = fmaf(wl, den, g_cd[i * CH_SZ + c]);
    }

    const size_t base = (size_t)b * T_SZ * D_SZ + (size_t)seg * SEG_LEN * D_SZ + d;
    const __half* kp = g_kh + base;
    const __half* vp = g_vh + base;
    const __half* rp = g_rh + base;
    float* op = out + base;

    for (int t = 0; t < SEG_LEN; t += 8) {
        float kk[8], vv[8], rr[8];
#pragma unroll
        for (int i = 0; i < 8; i++) {
            const size_t o = (size_t)(t + i) * D_SZ;
            kk[i] = __half2float(kp[o]);
            vv[i] = __half2float(vp[o]);
            rr[i] = __half2float(rp[o]);
        }
#pragma unroll
        for (int i = 0; i < 8; i++) {
            const float ek = expf(kk[i]);
            num = fmaf(w, num, ek * vv[i]);
            den = fmaf(w, den, ek);
            op[(size_t)(t + i) * D_SZ] = rr[i] * num / (den + 1e-8f);
        }
    }

    if (seg == 0) {
        float* out2 = out + (size_t)B_SZ * T_SZ * D_SZ;
        out2[c] = x[(size_t)b * T_SZ * D_SZ + (size_t)(T_SZ - 2) * D_SZ + d];
    }
}

// ---------------- launch --------------------------------------------------------
extern "C" void kernel_launch(void* const* d_in, const int* in_sizes, int n_in,
                              void* d_out, int out_size)
{
    const float* x  = (const float*)d_in[0];
    const float* Wk = (const float*)d_in[1];
    const float* Wv = (const float*)d_in[2];
    const float* Wr = (const float*)d_in[3];
    const float* td = (const float*)d_in[4];
    float* out = (float*)d_out;

    cudaFuncSetAttribute(gemm_hmma_kernel,
                         cudaFuncAttributeMaxDynamicSharedMemorySize, GEMM_SMEM);

    convert_all_kernel<<<(unsigned)((CV_TOTAL + 255) / 256), 256>>>(x, Wk, Wv, Wr);

    dim3 gg(D_SZ / BN, M_SZ / BM, 3);   // (16, 128, 3)
    gemm_hmma_kernel<<<gg, 256, GEMM_SMEM>>>();

    const int p1_total = (N_SEG - 1) * CH_SZ;   // 245760 threads
    wkv_p1_kernel<<<p1_total / 256, 256>>>(td);
    const int p2_total = N_SEG * CH_SZ;          // 262144 threads
    wkv_p2_kernel<<<p2_total / 256, 256>>>(td, x, out);
}

// round 13
// speedup vs baseline: 1.1512x; 1.0191x over previous
#include <cuda_runtime.h>
#include <cuda_fp16.h>
#include <cstdint>

// Problem constants (fixed: B=8, T=2048, D=2048)
#define B_SZ 8
#define T_SZ 2048
#define D_SZ 2048
#define M_SZ (B_SZ * T_SZ)        // 16384
#define CH_SZ (B_SZ * D_SZ)       // 16384 channels
#define CH2 (CH_SZ / 2)           // 8192 channel-pairs
#define SEG_LEN 64
#define N_SEG (T_SZ / SEG_LEN)    // 32

// ---------------- device scratch (static: no runtime allocation) ------------
__device__ __half g_xh[(size_t)M_SZ * D_SZ];     // fp16(x)
__device__ __half g_wh[(size_t)3 * D_SZ * D_SZ]; // fp16(W) for Wk,Wv,Wr
__device__ __half g_kh[(size_t)M_SZ * D_SZ];     // k (fp16)
__device__ __half g_vh[(size_t)M_SZ * D_SZ];     // v (fp16)
__device__ __half g_rh[(size_t)M_SZ * D_SZ];     // r (fp16)
__device__ float2 g_cn[(size_t)N_SEG * CH2];     // per-seg carry numerator (2ch)
__device__ float2 g_cd[(size_t)N_SEG * CH2];     // per-seg carry denominator

// ---------------- helpers -----------------------------------------------------
__device__ __forceinline__ uint32_t smem_u32(const void* p) {
    uint32_t a;
    asm("{ .reg .u64 t; cvta.to.shared.u64 t, %1; cvt.u32.u64 %0, t; }" : "=r"(a) : "l"(p));
    return a;
}
__device__ __forceinline__ void cp16(uint32_t dst, const void* src) {
    asm volatile("cp.async.cg.shared.global [%0], [%1], 16;" :: "r"(dst), "l"(src));
}
__device__ __forceinline__ void cp16z(uint32_t dst, const void* src, uint32_t src_sz) {
    asm volatile("cp.async.cg.shared.global [%0], [%1], 16, %2;"
                 :: "r"(dst), "l"(src), "r"(src_sz));
}
#define SWZ128(o) ((o) ^ (((o) >> 3) & 0x70))

__device__ __forceinline__ void ldsm_x4(uint32_t* r, uint32_t addr) {
    asm volatile("ldmatrix.sync.aligned.m8n8.x4.shared.b16 {%0,%1,%2,%3}, [%4];"
                 : "=r"(r[0]), "=r"(r[1]), "=r"(r[2]), "=r"(r[3]) : "r"(addr));
}
__device__ __forceinline__ void mma16816(float* c, const uint32_t* a, const uint32_t* b) {
    asm volatile(
        "mma.sync.aligned.m16n8k16.row.col.f32.f16.f16.f32 "
        "{%0,%1,%2,%3}, {%4,%5,%6,%7}, {%8,%9}, {%0,%1,%2,%3};"
        : "+f"(c[0]), "+f"(c[1]), "+f"(c[2]), "+f"(c[3])
        : "r"(a[0]), "r"(a[1]), "r"(a[2]), "r"(a[3]), "r"(b[0]), "r"(b[1]));
}

// ---------------- fused conversion: fp32 -> fp16 (x and all 3 W) ---------------
#define X_OCT ((size_t)M_SZ * D_SZ / 8)
#define W_OCT ((size_t)3 * D_SZ * D_SZ / 8)
#define CV_TOTAL (X_OCT + W_OCT)

__global__ void convert_all_kernel(const float* __restrict__ x,
                                   const float* __restrict__ Wk,
                                   const float* __restrict__ Wv,
                                   const float* __restrict__ Wr) {
    size_t q = (size_t)blockIdx.x * blockDim.x + threadIdx.x;
    if (q >= CV_TOTAL) return;
    const float* src;
    __half* dst;
    size_t i;
    if (q < X_OCT) {
        i = q * 8;
        src = x;
        dst = g_xh;
    } else {
        size_t wq = q - X_OCT;
        const size_t wsz = (size_t)D_SZ * D_SZ;
        size_t z = wq / (wsz / 8);
        i = (wq - z * (wsz / 8)) * 8;
        src = (z == 0) ? Wk : (z == 1) ? Wv : Wr;
        dst = g_wh + z * wsz;
    }
    float4 v0 = *(const float4*)(src + i);
    float4 v1 = *(const float4*)(src + i + 4);
    __half2* op = (__half2*)(dst + i);
    op[0] = __halves2half2(__float2half_rn(v0.x), __float2half_rn(v0.y));
    op[1] = __halves2half2(__float2half_rn(v0.z), __float2half_rn(v0.w));
    op[2] = __halves2half2(__float2half_rn(v1.x), __float2half_rn(v1.y));
    op[3] = __halves2half2(__float2half_rn(v1.z), __float2half_rn(v1.w));
}

// ---------------- HMMA GEMM (frozen config from R8/R11) ------------------------
#define BM 128
#define BN 128
#define BK 64
#define N_CHUNK (D_SZ / BK)        // 32
#define TILE_B 16384
#define STAGE_BYTES (2 * TILE_B)
#define N_STAGE 3
#define GEMM_SMEM (N_STAGE * STAGE_BYTES)   // 96 KB

__global__ __launch_bounds__(256, 2)
void gemm_hmma_kernel() {
    extern __shared__ char smem[];
    const uint32_t sbase = smem_u32(smem);
    const int tid = threadIdx.x;
    const int wid = tid >> 5;
    const int lane = tid & 31;
    const int wm = wid & 1;
    const int wn = wid >> 1;

    const int z = blockIdx.z;
    const int m0 = blockIdx.y * BM;
    const int n0 = blockIdx.x * BN;
    const bool shift = (z < 2);

    const __half* B_h = g_wh + (size_t)z * D_SZ * D_SZ;
    __half* Ch = (z == 0) ? g_kh : (z == 1) ? g_vh : g_rh;

    float acc[4][4][4];
#pragma unroll
    for (int i = 0; i < 4; i++)
#pragma unroll
        for (int j = 0; j < 4; j++)
#pragma unroll
            for (int q = 0; q < 4; q++) acc[i][j][q] = 0.f;

    auto load_stage = [&](int c, int s) {
        const int kt = c * BK;
        const uint32_t st = sbase + s * STAGE_BYTES;
#pragma unroll
        for (int it = 0; it < 4; it++) {
            const int i = tid + it * 256;
            const int row = i >> 3, seg = i & 7;
            const uint32_t sw = SWZ128((uint32_t)(row * 128 + seg * 16));
            const int rm = m0 + row;
            uint32_t sz = 16;
            int srow = rm;
            if (shift) {
                if ((rm & (T_SZ - 1)) == 0) sz = 0;
                else srow = rm - 1;
            }
            cp16z(st + sw, g_xh + (size_t)srow * D_SZ + kt + seg * 8, sz);
            cp16(st + TILE_B + sw, B_h + (size_t)(n0 + row) * D_SZ + kt + seg * 8);
        }
        asm volatile("cp.async.commit_group;" ::: "memory");
    };

    load_stage(0, 0);
    load_stage(1, 1);
    load_stage(2, 2);

    const int a_row = lane & 15;
    const int a_half = lane >> 4;
    const int b_nr = (lane & 7) + ((lane >> 4) << 3);
    const int b_half = (lane >> 3) & 1;

    int s = 0;
    int fs = 2;
    for (int c = 0; c < N_CHUNK; c++) {
        if (c == 0)                 asm volatile("cp.async.wait_group 2;" ::: "memory");
        else if (c == N_CHUNK - 1)  asm volatile("cp.async.wait_group 0;" ::: "memory");
        else                        asm volatile("cp.async.wait_group 1;" ::: "memory");
        __syncthreads();

        if (c >= 1 && c + 2 < N_CHUNK) load_stage(c + 2, fs);

        const uint32_t sA = sbase + s * STAGE_BYTES;
        const uint32_t sB = sA + TILE_B;

#pragma unroll
        for (int ks = 0; ks < 4; ks++) {
            uint32_t aa[4][4], bb[2][4];
#pragma unroll
            for (int mi = 0; mi < 4; mi++) {
                const uint32_t off = SWZ128(
                    (uint32_t)((wm * 64 + mi * 16 + a_row) * 128 + ks * 32 + a_half * 16));
                ldsm_x4(aa[mi], sA + off);
            }
#pragma unroll
            for (int j = 0; j < 2; j++) {
                const uint32_t off = SWZ128(
                    (uint32_t)((wn * 32 + j * 16 + b_nr) * 128 + ks * 32 + b_half * 16));
                ldsm_x4(bb[j], sB + off);
            }
#pragma unroll
            for (int mi = 0; mi < 4; mi++)
#pragma unroll
                for (int ni = 0; ni < 4; ni++)
                    mma16816(acc[mi][ni], aa[mi], &bb[ni >> 1][(ni & 1) * 2]);
        }
        fs = s;
        s = (s == N_STAGE - 1) ? 0 : s + 1;
    }

#pragma unroll
    for (int mi = 0; mi < 4; mi++) {
        const int gm = m0 + wm * 64 + mi * 16 + (lane >> 2);
#pragma unroll
        for (int ni = 0; ni < 4; ni++) {
            const int gn = n0 + wn * 32 + ni * 8 + (lane & 3) * 2;
            __half* p0 = Ch + (size_t)gm * D_SZ + gn;
            __half* p1 = p0 + 8 * D_SZ;
            *(__half2*)p0 = __halves2half2(__float2half_rn(acc[mi][ni][0]),
                                           __float2half_rn(acc[mi][ni][1]));
            *(__half2*)p1 = __halves2half2(__float2half_rn(acc[mi][ni][2]),
                                           __float2half_rn(acc[mi][ni][3]));
        }
    }
}

// ---------------- split WKV scan (2 channels/thread, 32 segments) --------------
// p1: carries for segments 0..N_SEG-2 (last segment's carry unused).
__global__ void wkv_p1_kernel(const float* __restrict__ time_decay) {
    const int gid = blockIdx.x * blockDim.x + threadIdx.x;  // < (N_SEG-1)*CH2
    const int c2 = gid & (CH2 - 1);
    const int seg = gid >> 13;
    const int c = c2 * 2;
    const int d = c & (D_SZ - 1);
    const int b = c >> 11;

    const float2 tdv = *(const float2*)(time_decay + d);
    const float wx = expf(-expf(tdv.x));
    const float wy = expf(-expf(tdv.y));

    const size_t base = (size_t)b * T_SZ * D_SZ + (size_t)seg * SEG_LEN * D_SZ + d;
    const __half2* kp = (const __half2*)(g_kh + base);
    const __half2* vp = (const __half2*)(g_vh + base);

    float nx = 0.f, ny = 0.f, dx = 0.f, dy = 0.f;
    for (int t = 0; t < SEG_LEN; t += 8) {
        float2 kk[8], vv[8];
#pragma unroll
        for (int i = 0; i < 8; i++) {
            const size_t o = (size_t)(t + i) * (D_SZ / 2);
            kk[i] = __half22float2(kp[o]);
            vv[i] = __half22float2(vp[o]);
        }
#pragma unroll
        for (int i = 0; i < 8; i++) {
            const float ekx = expf(kk[i].x);
            const float eky = expf(kk[i].y);
            nx = fmaf(wx, nx, ekx * vv[i].x);
            ny = fmaf(wy, ny, eky * vv[i].y);
            dx = fmaf(wx, dx, ekx);
            dy = fmaf(wy, dy, eky);
        }
    }
    g_cn[gid] = make_float2(nx, ny);
    g_cd[gid] = make_float2(dx, dy);
}

__global__ void wkv_p2_kernel(const float* __restrict__ time_decay,
                              const float* __restrict__ x,
                              float* __restrict__ out) {
    const int gid = blockIdx.x * blockDim.x + threadIdx.x;  // < N_SEG*CH2
    const int c2 = gid & (CH2 - 1);
    const int seg = gid >> 13;
    const int c = c2 * 2;
    const int d = c & (D_SZ - 1);
    const int b = c >> 11;

    const float2 tdv = *(const float2*)(time_decay + d);
    const float ex = expf(tdv.x), ey = expf(tdv.y);
    const float wx = expf(-ex), wy = expf(-ey);
    const float wlx = expf(-(float)SEG_LEN * ex);
    const float wly = expf(-(float)SEG_LEN * ey);

    float nx = 0.f, ny = 0.f, dx = 0.f, dy = 0.f;
    for (int i = 0; i < seg; i++) {
        const float2 cn = g_cn[i * CH2 + c2];
        const float2 cd = g_cd[i * CH2 + c2];
        nx = fmaf(wlx, nx, cn.x);
        ny = fmaf(wly, ny, cn.y);
        dx = fmaf(wlx, dx, cd.x);
        dy = fmaf(wly, dy, cd.y);
    }

    const size_t base = (size_t)b * T_SZ * D_SZ + (size_t)seg * SEG_LEN * D_SZ + d;
    const __half2* kp = (const __half2*)(g_kh + base);
    const __half2* vp = (const __half2*)(g_vh + base);
    const __half2* rp = (const __half2*)(g_rh + base);
    float* op = out + base;

    for (int t = 0; t < SEG_LEN; t += 8) {
        float2 kk[8], vv[8], rr[8];
#pragma unroll
        for (int i = 0; i < 8; i++) {
            const size_t o = (size_t)(t + i) * (D_SZ / 2);
            kk[i] = __half22float2(kp[o]);
            vv[i] = __half22float2(vp[o]);
            rr[i] = __half22float2(rp[o]);
        }
#pragma unroll
        for (int i = 0; i < 8; i++) {
            const float ekx = expf(kk[i].x);
            const float eky = expf(kk[i].y);
            nx = fmaf(wx, nx, ekx * vv[i].x);
            ny = fmaf(wy, ny, eky * vv[i].y);
            dx = fmaf(wx, dx, ekx);
            dy = fmaf(wy, dy, eky);
            float2 o2;
            o2.x = rr[i].x * nx / (dx + 1e-8f);
            o2.y = rr[i].y * ny / (dy + 1e-8f);
            *(float2*)(op + (size_t)(t + i) * D_SZ) = o2;
        }
    }

    if (seg == 0) {
        float* out2 = out + (size_t)B_SZ * T_SZ * D_SZ;
        *(float2*)(out2 + c) =
            *(const float2*)(x + (size_t)b * T_SZ * D_SZ + (size_t)(T_SZ - 2) * D_SZ + d);
    }
}

// ---------------- launch --------------------------------------------------------
extern "C" void kernel_launch(void* const* d_in, const int* in_sizes, int n_in,
                              void* d_out, int out_size)
{
    const float* x  = (const float*)d_in[0];
    const float* Wk = (const float*)d_in[1];
    const float* Wv = (const float*)d_in[2];
    const float* Wr = (const float*)d_in[3];
    const float* td = (const float*)d_in[4];
    float* out = (float*)d_out;

    cudaFuncSetAttribute(gemm_hmma_kernel,
                         cudaFuncAttributeMaxDynamicSharedMemorySize, GEMM_SMEM);

    convert_all_kernel<<<(unsigned)((CV_TOTAL + 255) / 256), 256>>>(x, Wk, Wv, Wr);

    dim3 gg(D_SZ / BN, M_SZ / BM, 3);   // (16, 128, 3)
    gemm_hmma_kernel<<<gg, 256, GEMM_SMEM>>>();

    const int p1_total = (N_SEG - 1) * CH2;   // 253952 threads
    wkv_p1_kernel<<<p1_total / 256, 256>>>(td);
    const int p2_total = N_SEG * CH2;          // 262144 threads
    wkv_p2_kernel<<<p2_total / 256, 256>>>(td, x, out);
}

// round 14
// speedup vs baseline: 1.1627x; 1.0100x over previous
#include <cuda_runtime.h>
#include <cuda_fp16.h>
#include <cstdint>

// Problem constants (fixed: B=8, T=2048, D=2048)
#define B_SZ 8
#define T_SZ 2048
#define D_SZ 2048
#define M_SZ (B_SZ * T_SZ)        // 16384
#define CH_SZ (B_SZ * D_SZ)       // 16384 channels
#define CH2 (CH_SZ / 2)           // 8192 channel-pairs
#define SEG_LEN 64
#define N_SEG (T_SZ / SEG_LEN)    // 32

// ---------------- device scratch (static: no runtime allocation) ------------
__device__ __half g_xh[(size_t)M_SZ * D_SZ];     // fp16(x)
__device__ __half g_wh[(size_t)3 * D_SZ * D_SZ]; // fp16(W) for Wk,Wv,Wr
__device__ __half g_kh[(size_t)M_SZ * D_SZ];     // k (fp16)
__device__ __half g_vh[(size_t)M_SZ * D_SZ];     // v (fp16)
__device__ __half g_rh[(size_t)M_SZ * D_SZ];     // r (fp16)
__device__ float2 g_cn[(size_t)N_SEG * CH2];     // per-seg carry numerator (2ch)
__device__ float2 g_cd[(size_t)N_SEG * CH2];     // per-seg carry denominator

// ---------------- helpers -----------------------------------------------------
__device__ __forceinline__ uint32_t smem_u32(const void* p) {
    uint32_t a;
    asm("{ .reg .u64 t; cvta.to.shared.u64 t, %1; cvt.u32.u64 %0, t; }" : "=r"(a) : "l"(p));
    return a;
}
__device__ __forceinline__ void cp16(uint32_t dst, const void* src) {
    asm volatile("cp.async.cg.shared.global [%0], [%1], 16;" :: "r"(dst), "l"(src));
}
__device__ __forceinline__ void cp16z(uint32_t dst, const void* src, uint32_t src_sz) {
    asm volatile("cp.async.cg.shared.global [%0], [%1], 16, %2;"
                 :: "r"(dst), "l"(src), "r"(src_sz));
}
#define SWZ128(o) ((o) ^ (((o) >> 3) & 0x70))

__device__ __forceinline__ void ldsm_x4(uint32_t* r, uint32_t addr) {
    asm volatile("ldmatrix.sync.aligned.m8n8.x4.shared.b16 {%0,%1,%2,%3}, [%4];"
                 : "=r"(r[0]), "=r"(r[1]), "=r"(r[2]), "=r"(r[3]) : "r"(addr));
}
__device__ __forceinline__ void mma16816(float* c, const uint32_t* a, const uint32_t* b) {
    asm volatile(
        "mma.sync.aligned.m16n8k16.row.col.f32.f16.f16.f32 "
        "{%0,%1,%2,%3}, {%4,%5,%6,%7}, {%8,%9}, {%0,%1,%2,%3};"
        : "+f"(c[0]), "+f"(c[1]), "+f"(c[2]), "+f"(c[3])
        : "r"(a[0]), "r"(a[1]), "r"(a[2]), "r"(a[3]), "r"(b[0]), "r"(b[1]));
}

// ---------------- fused conversion: fp32 -> fp16 (x and all 3 W) ---------------
#define X_OCT ((size_t)M_SZ * D_SZ / 8)
#define W_OCT ((size_t)3 * D_SZ * D_SZ / 8)
#define CV_TOTAL (X_OCT + W_OCT)

__global__ void convert_all_kernel(const float* __restrict__ x,
                                   const float* __restrict__ Wk,
                                   const float* __restrict__ Wv,
                                   const float* __restrict__ Wr) {
    size_t q = (size_t)blockIdx.x * blockDim.x + threadIdx.x;
    if (q >= CV_TOTAL) return;
    const float* src;
    __half* dst;
    size_t i;
    if (q < X_OCT) {
        i = q * 8;
        src = x;
        dst = g_xh;
    } else {
        size_t wq = q - X_OCT;
        const size_t wsz = (size_t)D_SZ * D_SZ;
        size_t z = wq / (wsz / 8);
        i = (wq - z * (wsz / 8)) * 8;
        src = (z == 0) ? Wk : (z == 1) ? Wv : Wr;
        dst = g_wh + z * wsz;
    }
    float4 v0 = *(const float4*)(src + i);
    float4 v1 = *(const float4*)(src + i + 4);
    __half2* op = (__half2*)(dst + i);
    op[0] = __halves2half2(__float2half_rn(v0.x), __float2half_rn(v0.y));
    op[1] = __halves2half2(__float2half_rn(v0.z), __float2half_rn(v0.w));
    op[2] = __halves2half2(__float2half_rn(v1.x), __float2half_rn(v1.y));
    op[3] = __halves2half2(__float2half_rn(v1.z), __float2half_rn(v1.w));
}

// ---------------- HMMA GEMM (frozen config from R8/R11) ------------------------
#define BM 128
#define BN 128
#define BK 64
#define N_CHUNK (D_SZ / BK)        // 32
#define TILE_B 16384
#define STAGE_BYTES (2 * TILE_B)
#define N_STAGE 3
#define GEMM_SMEM (N_STAGE * STAGE_BYTES)   // 96 KB

__global__ __launch_bounds__(256, 2)
void gemm_hmma_kernel() {
    extern __shared__ char smem[];
    const uint32_t sbase = smem_u32(smem);
    const int tid = threadIdx.x;
    const int wid = tid >> 5;
    const int lane = tid & 31;
    const int wm = wid & 1;
    const int wn = wid >> 1;

    const int z = blockIdx.z;
    const int m0 = blockIdx.y * BM;
    const int n0 = blockIdx.x * BN;
    const bool shift = (z < 2);

    const __half* B_h = g_wh + (size_t)z * D_SZ * D_SZ;
    __half* Ch = (z == 0) ? g_kh : (z == 1) ? g_vh : g_rh;

    float acc[4][4][4];
#pragma unroll
    for (int i = 0; i < 4; i++)
#pragma unroll
        for (int j = 0; j < 4; j++)
#pragma unroll
            for (int q = 0; q < 4; q++) acc[i][j][q] = 0.f;

    auto load_stage = [&](int c, int s) {
        const int kt = c * BK;
        const uint32_t st = sbase + s * STAGE_BYTES;
#pragma unroll
        for (int it = 0; it < 4; it++) {
            const int i = tid + it * 256;
            const int row = i >> 3, seg = i & 7;
            const uint32_t sw = SWZ128((uint32_t)(row * 128 + seg * 16));
            const int rm = m0 + row;
            uint32_t sz = 16;
            int srow = rm;
            if (shift) {
                if ((rm & (T_SZ - 1)) == 0) sz = 0;
                else srow = rm - 1;
            }
            cp16z(st + sw, g_xh + (size_t)srow * D_SZ + kt + seg * 8, sz);
            cp16(st + TILE_B + sw, B_h + (size_t)(n0 + row) * D_SZ + kt + seg * 8);
        }
        asm volatile("cp.async.commit_group;" ::: "memory");
    };

    load_stage(0, 0);
    load_stage(1, 1);
    load_stage(2, 2);

    const int a_row = lane & 15;
    const int a_half = lane >> 4;
    const int b_nr = (lane & 7) + ((lane >> 4) << 3);
    const int b_half = (lane >> 3) & 1;

    int s = 0;
    int fs = 2;
    for (int c = 0; c < N_CHUNK; c++) {
        if (c == 0)                 asm volatile("cp.async.wait_group 2;" ::: "memory");
        else if (c == N_CHUNK - 1)  asm volatile("cp.async.wait_group 0;" ::: "memory");
        else                        asm volatile("cp.async.wait_group 1;" ::: "memory");
        __syncthreads();

        if (c >= 1 && c + 2 < N_CHUNK) load_stage(c + 2, fs);

        const uint32_t sA = sbase + s * STAGE_BYTES;
        const uint32_t sB = sA + TILE_B;

#pragma unroll
        for (int ks = 0; ks < 4; ks++) {
            uint32_t aa[4][4], bb[2][4];
#pragma unroll
            for (int mi = 0; mi < 4; mi++) {
                const uint32_t off = SWZ128(
                    (uint32_t)((wm * 64 + mi * 16 + a_row) * 128 + ks * 32 + a_half * 16));
                ldsm_x4(aa[mi], sA + off);
            }
#pragma unroll
            for (int j = 0; j < 2; j++) {
                const uint32_t off = SWZ128(
                    (uint32_t)((wn * 32 + j * 16 + b_nr) * 128 + ks * 32 + b_half * 16));
                ldsm_x4(bb[j], sB + off);
            }
#pragma unroll
            for (int mi = 0; mi < 4; mi++)
#pragma unroll
                for (int ni = 0; ni < 4; ni++)
                    mma16816(acc[mi][ni], aa[mi], &bb[ni >> 1][(ni & 1) * 2]);
        }
        fs = s;
        s = (s == N_STAGE - 1) ? 0 : s + 1;
    }

#pragma unroll
    for (int mi = 0; mi < 4; mi++) {
        const int gm = m0 + wm * 64 + mi * 16 + (lane >> 2);
#pragma unroll
        for (int ni = 0; ni < 4; ni++) {
            const int gn = n0 + wn * 32 + ni * 8 + (lane & 3) * 2;
            __half* p0 = Ch + (size_t)gm * D_SZ + gn;
            __half* p1 = p0 + 8 * D_SZ;
            *(__half2*)p0 = __halves2half2(__float2half_rn(acc[mi][ni][0]),
                                           __float2half_rn(acc[mi][ni][1]));
            *(__half2*)p1 = __halves2half2(__float2half_rn(acc[mi][ni][2]),
                                           __float2half_rn(acc[mi][ni][3]));
        }
    }
}

// ---------------- split WKV scan (2 channels/thread, 32 segments) --------------
// Fast transcendentals: __expf (MUFU ex2) and __fdividef (MUFU rcp) — error
// ~5e-7 / ~2ulp, negligible vs the 5.4e-4 quantization error budget.
__global__ void wkv_p1_kernel(const float* __restrict__ time_decay) {
    const int gid = blockIdx.x * blockDim.x + threadIdx.x;  // < (N_SEG-1)*CH2
    const int c2 = gid & (CH2 - 1);
    const int seg = gid >> 13;
    const int c = c2 * 2;
    const int d = c & (D_SZ - 1);
    const int b = c >> 11;

    const float2 tdv = *(const float2*)(time_decay + d);
    const float wx = __expf(-__expf(tdv.x));
    const float wy = __expf(-__expf(tdv.y));

    const size_t base = (size_t)b * T_SZ * D_SZ + (size_t)seg * SEG_LEN * D_SZ + d;
    const __half2* kp = (const __half2*)(g_kh + base);
    const __half2* vp = (const __half2*)(g_vh + base);

    float nx = 0.f, ny = 0.f, dx = 0.f, dy = 0.f;
    for (int t = 0; t < SEG_LEN; t += 8) {
        float2 kk[8], vv[8];
#pragma unroll
        for (int i = 0; i < 8; i++) {
            const size_t o = (size_t)(t + i) * (D_SZ / 2);
            kk[i] = __half22float2(kp[o]);
            vv[i] = __half22float2(vp[o]);
        }
#pragma unroll
        for (int i = 0; i < 8; i++) {
            const float ekx = __expf(kk[i].x);
            const float eky = __expf(kk[i].y);
            nx = fmaf(wx, nx, ekx * vv[i].x);
            ny = fmaf(wy, ny, eky * vv[i].y);
            dx = fmaf(wx, dx, ekx);
            dy = fmaf(wy, dy, eky);
        }
    }
    g_cn[gid] = make_float2(nx, ny);
    g_cd[gid] = make_float2(dx, dy);
}

__global__ void wkv_p2_kernel(const float* __restrict__ time_decay,
                              const float* __restrict__ x,
                              float* __restrict__ out) {
    const int gid = blockIdx.x * blockDim.x + threadIdx.x;  // < N_SEG*CH2
    const int c2 = gid & (CH2 - 1);
    const int seg = gid >> 13;
    const int c = c2 * 2;
    const int d = c & (D_SZ - 1);
    const int b = c >> 11;

    const float2 tdv = *(const float2*)(time_decay + d);
    const float ex = __expf(tdv.x), ey = __expf(tdv.y);
    const float wx = __expf(-ex), wy = __expf(-ey);
    const float wlx = __expf(-(float)SEG_LEN * ex);
    const float wly = __expf(-(float)SEG_LEN * ey);

    float nx = 0.f, ny = 0.f, dx = 0.f, dy = 0.f;
    for (int i = 0; i < seg; i++) {
        const float2 cn = g_cn[i * CH2 + c2];
        const float2 cd = g_cd[i * CH2 + c2];
        nx = fmaf(wlx, nx, cn.x);
        ny = fmaf(wly, ny, cn.y);
        dx = fmaf(wlx, dx, cd.x);
        dy = fmaf(wly, dy, cd.y);
    }

    const size_t base = (size_t)b * T_SZ * D_SZ + (size_t)seg * SEG_LEN * D_SZ + d;
    const __half2* kp = (const __half2*)(g_kh + base);
    const __half2* vp = (const __half2*)(g_vh + base);
    const __half2* rp = (const __half2*)(g_rh + base);
    float* op = out + base;

    for (int t = 0; t < SEG_LEN; t += 8) {
        float2 kk[8], vv[8], rr[8];
#pragma unroll
        for (int i = 0; i < 8; i++) {
            const size_t o = (size_t)(t + i) * (D_SZ / 2);
            kk[i] = __half22float2(kp[o]);
            vv[i] = __half22float2(vp[o]);
            rr[i] = __half22float2(rp[o]);
        }
#pragma unroll
        for (int i = 0; i < 8; i++) {
            const float ekx = __expf(kk[i].x);
            const float eky = __expf(kk[i].y);
            nx = fmaf(wx, nx, ekx * vv[i].x);
            ny = fmaf(wy, ny, eky * vv[i].y);
            dx = fmaf(wx, dx, ekx);
            dy = fmaf(wy, dy, eky);
            float2 o2;
            o2.x = rr[i].x * __fdividef(nx, dx + 1e-8f);
            o2.y = rr[i].y * __fdividef(ny, dy + 1e-8f);
            *(float2*)(op + (size_t)(t + i) * D_SZ) = o2;
        }
    }

    if (seg == 0) {
        float* out2 = out + (size_t)B_SZ * T_SZ * D_SZ;
        *(float2*)(out2 + c) =
            *(const float2*)(x + (size_t)b * T_SZ * D_SZ + (size_t)(T_SZ - 2) * D_SZ + d);
    }
}

// ---------------- launch --------------------------------------------------------
extern "C" void kernel_launch(void* const* d_in, const int* in_sizes, int n_in,
                              void* d_out, int out_size)
{
    const float* x  = (const float*)d_in[0];
    const float* Wk = (const float*)d_in[1];
    const float* Wv = (const float*)d_in[2];
    const float* Wr = (const float*)d_in[3];
    const float* td = (const float*)d_in[4];
    float* out = (float*)d_out;

    cudaFuncSetAttribute(gemm_hmma_kernel,
                         cudaFuncAttributeMaxDynamicSharedMemorySize, GEMM_SMEM);

    convert_all_kernel<<<(unsigned)((CV_TOTAL + 255) / 256), 256>>>(x, Wk, Wv, Wr);

    dim3 gg(D_SZ / BN, M_SZ / BM, 3);   // (16, 128, 3)
    gemm_hmma_kernel<<<gg, 256, GEMM_SMEM>>>();

    const int p1_total = (N_SEG - 1) * CH2;   // 253952 threads
    wkv_p1_kernel<<<p1_total / 256, 256>>>(td);
    const int p2_total = N_SEG * CH2;          // 262144 threads
    wkv_p2_kernel<<<p2_total / 256, 256>>>(td, x, out);
}

// round 15
// speedup vs baseline: 1.1861x; 1.0202x over previous
#include <cuda_runtime.h>
#include <cuda_fp16.h>
#include <cstdint>

// Problem constants (fixed: B=8, T=2048, D=2048)
#define B_SZ 8
#define T_SZ 2048
#define D_SZ 2048
#define M_SZ (B_SZ * T_SZ)        // 16384
#define CH_SZ (B_SZ * D_SZ)       // 16384 channels
#define CH2 (CH_SZ / 2)           // 8192 channel-pairs
#define SEG_LEN 64
#define N_SEG (T_SZ / SEG_LEN)    // 32

// ---------------- device scratch (static: no runtime allocation) ------------
__device__ __half g_xh[(size_t)M_SZ * D_SZ];     // fp16(x)
__device__ __half g_wh[(size_t)3 * D_SZ * D_SZ]; // fp16(W) for Wk,Wv,Wr
__device__ __half g_kh[(size_t)M_SZ * D_SZ];     // k (fp16)
__device__ __half g_vh[(size_t)M_SZ * D_SZ];     // v (fp16)
__device__ __half g_rh[(size_t)M_SZ * D_SZ];     // r (fp16)
__device__ float2 g_cn[(size_t)N_SEG * CH2];     // per-seg carry numerator (2ch)
__device__ float2 g_cd[(size_t)N_SEG * CH2];     // per-seg carry denominator

// ---------------- helpers -----------------------------------------------------
__device__ __forceinline__ uint32_t smem_u32(const void* p) {
    uint32_t a;
    asm("{ .reg .u64 t; cvta.to.shared.u64 t, %1; cvt.u32.u64 %0, t; }" : "=r"(a) : "l"(p));
    return a;
}
__device__ __forceinline__ void cp16(uint32_t dst, const void* src) {
    asm volatile("cp.async.cg.shared.global [%0], [%1], 16;" :: "r"(dst), "l"(src));
}
__device__ __forceinline__ void cp16z(uint32_t dst, const void* src, uint32_t src_sz) {
    asm volatile("cp.async.cg.shared.global [%0], [%1], 16, %2;"
                 :: "r"(dst), "l"(src), "r"(src_sz));
}
#define SWZ128(o) ((o) ^ (((o) >> 3) & 0x70))

__device__ __forceinline__ void ldsm_x4(uint32_t* r, uint32_t addr) {
    asm volatile("ldmatrix.sync.aligned.m8n8.x4.shared.b16 {%0,%1,%2,%3}, [%4];"
                 : "=r"(r[0]), "=r"(r[1]), "=r"(r[2]), "=r"(r[3]) : "r"(addr));
}
__device__ __forceinline__ void mma16816(float* c, const uint32_t* a, const uint32_t* b) {
    asm volatile(
        "mma.sync.aligned.m16n8k16.row.col.f32.f16.f16.f32 "
        "{%0,%1,%2,%3}, {%4,%5,%6,%7}, {%8,%9}, {%0,%1,%2,%3};"
        : "+f"(c[0]), "+f"(c[1]), "+f"(c[2]), "+f"(c[3])
        : "r"(a[0]), "r"(a[1]), "r"(a[2]), "r"(a[3]), "r"(b[0]), "r"(b[1]));
}

// ---------------- fused conversion: fp32 -> fp16 (x and all 3 W) ---------------
#define X_OCT ((size_t)M_SZ * D_SZ / 8)
#define W_OCT ((size_t)3 * D_SZ * D_SZ / 8)
#define CV_TOTAL (X_OCT + W_OCT)

__global__ void convert_all_kernel(const float* __restrict__ x,
                                   const float* __restrict__ Wk,
                                   const float* __restrict__ Wv,
                                   const float* __restrict__ Wr) {
    size_t q = (size_t)blockIdx.x * blockDim.x + threadIdx.x;
    if (q >= CV_TOTAL) return;
    const float* src;
    __half* dst;
    size_t i;
    if (q < X_OCT) {
        i = q * 8;
        src = x;
        dst = g_xh;
    } else {
        size_t wq = q - X_OCT;
        const size_t wsz = (size_t)D_SZ * D_SZ;
        size_t z = wq / (wsz / 8);
        i = (wq - z * (wsz / 8)) * 8;
        src = (z == 0) ? Wk : (z == 1) ? Wv : Wr;
        dst = g_wh + z * wsz;
    }
    float4 v0 = *(const float4*)(src + i);
    float4 v1 = *(const float4*)(src + i + 4);
    __half2* op = (__half2*)(dst + i);
    op[0] = __halves2half2(__float2half_rn(v0.x), __float2half_rn(v0.y));
    op[1] = __halves2half2(__float2half_rn(v0.z), __float2half_rn(v0.w));
    op[2] = __halves2half2(__float2half_rn(v1.x), __float2half_rn(v1.y));
    op[3] = __halves2half2(__float2half_rn(v1.z), __float2half_rn(v1.w));
}

// ---------------- GEMM device body (frozen config from R8/R11) -----------------
#define BM 128
#define BN 128
#define BK 64
#define N_CHUNK (D_SZ / BK)        // 32
#define TILE_B 16384
#define STAGE_BYTES (2 * TILE_B)
#define N_STAGE 3
#define GEMM_SMEM (N_STAGE * STAGE_BYTES)   // 96 KB
#define N_GEMM_XY ((D_SZ / BN) * (M_SZ / BM))   // 2048 tiles per z

__device__ __forceinline__ void gemm_tile_body(int z, int bx, int by, char* smem) {
    const uint32_t sbase = smem_u32(smem);
    const int tid = threadIdx.x;
    const int wid = tid >> 5;
    const int lane = tid & 31;
    const int wm = wid & 1;
    const int wn = wid >> 1;

    const int m0 = by * BM;
    const int n0 = bx * BN;
    const bool shift = (z < 2);

    const __half* B_h = g_wh + (size_t)z * D_SZ * D_SZ;
    __half* Ch = (z == 0) ? g_kh : (z == 1) ? g_vh : g_rh;

    float acc[4][4][4];
#pragma unroll
    for (int i = 0; i < 4; i++)
#pragma unroll
        for (int j = 0; j < 4; j++)
#pragma unroll
            for (int q = 0; q < 4; q++) acc[i][j][q] = 0.f;

    auto load_stage = [&](int c, int s) {
        const int kt = c * BK;
        const uint32_t st = sbase + s * STAGE_BYTES;
#pragma unroll
        for (int it = 0; it < 4; it++) {
            const int i = tid + it * 256;
            const int row = i >> 3, seg = i & 7;
            const uint32_t sw = SWZ128((uint32_t)(row * 128 + seg * 16));
            const int rm = m0 + row;
            uint32_t sz = 16;
            int srow = rm;
            if (shift) {
                if ((rm & (T_SZ - 1)) == 0) sz = 0;
                else srow = rm - 1;
            }
            cp16z(st + sw, g_xh + (size_t)srow * D_SZ + kt + seg * 8, sz);
            cp16(st + TILE_B + sw, B_h + (size_t)(n0 + row) * D_SZ + kt + seg * 8);
        }
        asm volatile("cp.async.commit_group;" ::: "memory");
    };

    load_stage(0, 0);
    load_stage(1, 1);
    load_stage(2, 2);

    const int a_row = lane & 15;
    const int a_half = lane >> 4;
    const int b_nr = (lane & 7) + ((lane >> 4) << 3);
    const int b_half = (lane >> 3) & 1;

    int s = 0;
    int fs = 2;
    for (int c = 0; c < N_CHUNK; c++) {
        if (c == 0)                 asm volatile("cp.async.wait_group 2;" ::: "memory");
        else if (c == N_CHUNK - 1)  asm volatile("cp.async.wait_group 0;" ::: "memory");
        else                        asm volatile("cp.async.wait_group 1;" ::: "memory");
        __syncthreads();

        if (c >= 1 && c + 2 < N_CHUNK) load_stage(c + 2, fs);

        const uint32_t sA = sbase + s * STAGE_BYTES;
        const uint32_t sB = sA + TILE_B;

#pragma unroll
        for (int ks = 0; ks < 4; ks++) {
            uint32_t aa[4][4], bb[2][4];
#pragma unroll
            for (int mi = 0; mi < 4; mi++) {
                const uint32_t off = SWZ128(
                    (uint32_t)((wm * 64 + mi * 16 + a_row) * 128 + ks * 32 + a_half * 16));
                ldsm_x4(aa[mi], sA + off);
            }
#pragma unroll
            for (int j = 0; j < 2; j++) {
                const uint32_t off = SWZ128(
                    (uint32_t)((wn * 32 + j * 16 + b_nr) * 128 + ks * 32 + b_half * 16));
                ldsm_x4(bb[j], sB + off);
            }
#pragma unroll
            for (int mi = 0; mi < 4; mi++)
#pragma unroll
                for (int ni = 0; ni < 4; ni++)
                    mma16816(acc[mi][ni], aa[mi], &bb[ni >> 1][(ni & 1) * 2]);
        }
        fs = s;
        s = (s == N_STAGE - 1) ? 0 : s + 1;
    }

#pragma unroll
    for (int mi = 0; mi < 4; mi++) {
        const int gm = m0 + wm * 64 + mi * 16 + (lane >> 2);
#pragma unroll
        for (int ni = 0; ni < 4; ni++) {
            const int gn = n0 + wn * 32 + ni * 8 + (lane & 3) * 2;
            __half* p0 = Ch + (size_t)gm * D_SZ + gn;
            __half* p1 = p0 + 8 * D_SZ;
            *(__half2*)p0 = __halves2half2(__float2half_rn(acc[mi][ni][0]),
                                           __float2half_rn(acc[mi][ni][1]));
            *(__half2*)p1 = __halves2half2(__float2half_rn(acc[mi][ni][2]),
                                           __float2half_rn(acc[mi][ni][3]));
        }
    }
}

// ---------------- p1 device body (2 channels/thread) ---------------------------
__device__ __forceinline__ void wkv_p1_body(int gid, const float* __restrict__ time_decay) {
    const int c2 = gid & (CH2 - 1);
    const int seg = gid >> 13;
    const int c = c2 * 2;
    const int d = c & (D_SZ - 1);
    const int b = c >> 11;

    const float2 tdv = *(const float2*)(time_decay + d);
    const float wx = __expf(-__expf(tdv.x));
    const float wy = __expf(-__expf(tdv.y));

    const size_t base = (size_t)b * T_SZ * D_SZ + (size_t)seg * SEG_LEN * D_SZ + d;
    const __half2* kp = (const __half2*)(g_kh + base);
    const __half2* vp = (const __half2*)(g_vh + base);

    float nx = 0.f, ny = 0.f, dx = 0.f, dy = 0.f;
    for (int t = 0; t < SEG_LEN; t += 8) {
        float2 kk[8], vv[8];
#pragma unroll
        for (int i = 0; i < 8; i++) {
            const size_t o = (size_t)(t + i) * (D_SZ / 2);
            kk[i] = __half22float2(kp[o]);
            vv[i] = __half22float2(vp[o]);
        }
#pragma unroll
        for (int i = 0; i < 8; i++) {
            const float ekx = __expf(kk[i].x);
            const float eky = __expf(kk[i].y);
            nx = fmaf(wx, nx, ekx * vv[i].x);
            ny = fmaf(wy, ny, eky * vv[i].y);
            dx = fmaf(wx, dx, ekx);
            dy = fmaf(wy, dy, eky);
        }
    }
    g_cn[gid] = make_float2(nx, ny);
    g_cd[gid] = make_float2(dx, dy);
}

// ---------------- kernel 1: k,v GEMMs (z = 0,1) --------------------------------
__global__ __launch_bounds__(256, 2)
void gemm_kv_kernel() {
    extern __shared__ char smem[];
    gemm_tile_body(blockIdx.z, blockIdx.x, blockIdx.y, smem);
}

// ---------------- kernel 2: r GEMM interleaved with p1 --------------------------
// Flat grid of 3040 blocks. For b < 2976: every 3rd block (b%3==2) is a p1
// block (992 total); the other two are r-GEMM tiles. Blocks 2976..3039 are the
// remaining 64 r-GEMM tiles. Interleaving spreads p1 across all waves so its
// memory-bound work hides under the GEMM's tensor-issue-bound work.
#define N_P1_BLK ((N_SEG - 1) * CH2 / 256)        // 992
#define MERGE_BLKS (N_GEMM_XY + N_P1_BLK)         // 3040
#define INTERLEAVE_END (3 * N_P1_BLK)             // 2976

__global__ __launch_bounds__(256, 2)
void gemm_r_p1_kernel(const float* __restrict__ time_decay) {
    extern __shared__ char smem[];
    const int b = blockIdx.x;
    int gemm_idx = -1;
    int p1_blk = -1;
    if (b < INTERLEAVE_END) {
        if ((b % 3) == 2) p1_blk = b / 3;
        else              gemm_idx = (b / 3) * 2 + (b % 3);
    } else {
        gemm_idx = 2 * N_P1_BLK + (b - INTERLEAVE_END);   // 1984..2047
    }

    if (p1_blk >= 0) {
        wkv_p1_body(p1_blk * 256 + threadIdx.x, time_decay);
    } else {
        const int bx = gemm_idx & ((D_SZ / BN) - 1);   // 16 n-tiles
        const int by = gemm_idx >> 4;
        gemm_tile_body(2, bx, by, smem);
    }
}

// ---------------- p2: final scan + output --------------------------------------
__global__ void wkv_p2_kernel(const float* __restrict__ time_decay,
                              const float* __restrict__ x,
                              float* __restrict__ out) {
    const int gid = blockIdx.x * blockDim.x + threadIdx.x;  // < N_SEG*CH2
    const int c2 = gid & (CH2 - 1);
    const int seg = gid >> 13;
    const int c = c2 * 2;
    const int d = c & (D_SZ - 1);
    const int b = c >> 11;

    const float2 tdv = *(const float2*)(time_decay + d);
    const float ex = __expf(tdv.x), ey = __expf(tdv.y);
    const float wx = __expf(-ex), wy = __expf(-ey);
    const float wlx = __expf(-(float)SEG_LEN * ex);
    const float wly = __expf(-(float)SEG_LEN * ey);

    float nx = 0.f, ny = 0.f, dx = 0.f, dy = 0.f;
    for (int i = 0; i < seg; i++) {
        const float2 cn = g_cn[i * CH2 + c2];
        const float2 cd = g_cd[i * CH2 + c2];
        nx = fmaf(wlx, nx, cn.x);
        ny = fmaf(wly, ny, cn.y);
        dx = fmaf(wlx, dx, cd.x);
        dy = fmaf(wly, dy, cd.y);
    }

    const size_t base = (size_t)b * T_SZ * D_SZ + (size_t)seg * SEG_LEN * D_SZ + d;
    const __half2* kp = (const __half2*)(g_kh + base);
    const __half2* vp = (const __half2*)(g_vh + base);
    const __half2* rp = (const __half2*)(g_rh + base);
    float* op = out + base;

    for (int t = 0; t < SEG_LEN; t += 8) {
        float2 kk[8], vv[8], rr[8];
#pragma unroll
        for (int i = 0; i < 8; i++) {
            const size_t o = (size_t)(t + i) * (D_SZ / 2);
            kk[i] = __half22float2(kp[o]);
            vv[i] = __half22float2(vp[o]);
            rr[i] = __half22float2(rp[o]);
        }
#pragma unroll
        for (int i = 0; i < 8; i++) {
            const float ekx = __expf(kk[i].x);
            const float eky = __expf(kk[i].y);
            nx = fmaf(wx, nx, ekx * vv[i].x);
            ny = fmaf(wy, ny, eky * vv[i].y);
            dx = fmaf(wx, dx, ekx);
            dy = fmaf(wy, dy, eky);
            float2 o2;
            o2.x = rr[i].x * __fdividef(nx, dx + 1e-8f);
            o2.y = rr[i].y * __fdividef(ny, dy + 1e-8f);
            *(float2*)(op + (size_t)(t + i) * D_SZ) = o2;
        }
    }

    if (seg == 0) {
        float* out2 = out + (size_t)B_SZ * T_SZ * D_SZ;
        *(float2*)(out2 + c) =
            *(const float2*)(x + (size_t)b * T_SZ * D_SZ + (size_t)(T_SZ - 2) * D_SZ + d);
    }
}

// ---------------- launch --------------------------------------------------------
extern "C" void kernel_launch(void* const* d_in, const int* in_sizes, int n_in,
                              void* d_out, int out_size)
{
    const float* x  = (const float*)d_in[0];
    const float* Wk = (const float*)d_in[1];
    const float* Wv = (const float*)d_in[2];
    const float* Wr = (const float*)d_in[3];
    const float* td = (const float*)d_in[4];
    float* out = (float*)d_out;

    cudaFuncSetAttribute(gemm_kv_kernel,
                         cudaFuncAttributeMaxDynamicSharedMemorySize, GEMM_SMEM);
    cudaFuncSetAttribute(gemm_r_p1_kernel,
                         cudaFuncAttributeMaxDynamicSharedMemorySize, GEMM_SMEM);

    convert_all_kernel<<<(unsigned)((CV_TOTAL + 255) / 256), 256>>>(x, Wk, Wv, Wr);

    dim3 gkv(D_SZ / BN, M_SZ / BM, 2);   // (16, 128, 2): k and v
    gemm_kv_kernel<<<gkv, 256, GEMM_SMEM>>>();

    gemm_r_p1_kernel<<<MERGE_BLKS, 256, GEMM_SMEM>>>(td);   // r GEMM + p1 overlapped

    const int p2_total = N_SEG * CH2;    // 262144 threads
    wkv_p2_kernel<<<p2_total / 256, 256>>>(td, x, out);
}